// round 4
// baseline (speedup 1.0000x reference)
#include <cuda_runtime.h>
#include <math.h>

#define B_  4
#define S_  2048
#define D_  1024
#define H_  16
#define HD_ 64
#define M_  (B_*S_)

// Scratch (allocation-free rule: __device__ globals)
__device__ float g_q[M_*D_];
__device__ float g_k[M_*D_];
__device__ float g_v[M_*D_];
__device__ float g_ctx[M_*D_];

// ---------------------------------------------------------------------------
// GEMM: out[m,n] = sum_k A[m,k] * W[n,k] + bias[n]     (M=8192, N=K=1024)
// 128x128 tile, BK=8, 256 threads, 8x8 micro-tile.
// ---------------------------------------------------------------------------
__global__ __launch_bounds__(256) void gemm_nt(const float* __restrict__ A,
                                               const float* __restrict__ W,
                                               const float* __restrict__ bias,
                                               float* __restrict__ out)
{
    __shared__ float As[8][128];
    __shared__ float Bs[8][128];

    const int tid  = threadIdx.x;
    const int arow = tid >> 1;          // 0..127
    const int ac   = (tid & 1) * 4;     // 0 or 4
    const int ty   = tid >> 4;          // 0..15
    const int tx   = tid & 15;          // 0..15
    const int row0 = ty * 8;
    const int col0 = tx * 8;

    const float* Aptr = A + (size_t)(blockIdx.y * 128 + arow) * D_ + ac;
    const float* Wptr = W + (size_t)(blockIdx.x * 128 + arow) * D_ + ac;

    float acc[8][8];
    #pragma unroll
    for (int i = 0; i < 8; i++)
        #pragma unroll
        for (int j = 0; j < 8; j++) acc[i][j] = 0.f;

    for (int k0 = 0; k0 < D_; k0 += 8) {
        float4 av = *(const float4*)(Aptr + k0);
        float4 wv = *(const float4*)(Wptr + k0);
        __syncthreads();
        As[ac+0][arow] = av.x; As[ac+1][arow] = av.y;
        As[ac+2][arow] = av.z; As[ac+3][arow] = av.w;
        Bs[ac+0][arow] = wv.x; Bs[ac+1][arow] = wv.y;
        Bs[ac+2][arow] = wv.z; Bs[ac+3][arow] = wv.w;
        __syncthreads();

        #pragma unroll
        for (int k = 0; k < 8; k++) {
            float a[8], b[8];
            *(float4*)&a[0] = *(const float4*)&As[k][row0];
            *(float4*)&a[4] = *(const float4*)&As[k][row0 + 4];
            *(float4*)&b[0] = *(const float4*)&Bs[k][col0];
            *(float4*)&b[4] = *(const float4*)&Bs[k][col0 + 4];
            #pragma unroll
            for (int i = 0; i < 8; i++)
                #pragma unroll
                for (int j = 0; j < 8; j++)
                    acc[i][j] = fmaf(a[i], b[j], acc[i][j]);
        }
    }

    const int gn = blockIdx.x * 128 + col0;
    float4 bi0 = *(const float4*)&bias[gn];
    float4 bi1 = *(const float4*)&bias[gn + 4];
    #pragma unroll
    for (int i = 0; i < 8; i++) {
        size_t off = (size_t)(blockIdx.y * 128 + row0 + i) * D_ + gn;
        float4 r0, r1;
        r0.x = acc[i][0] + bi0.x; r0.y = acc[i][1] + bi0.y;
        r0.z = acc[i][2] + bi0.z; r0.w = acc[i][3] + bi0.w;
        r1.x = acc[i][4] + bi1.x; r1.y = acc[i][5] + bi1.y;
        r1.z = acc[i][6] + bi1.z; r1.w = acc[i][7] + bi1.w;
        *(float4*)&out[off]     = r0;
        *(float4*)&out[off + 4] = r1;
    }
}

// ---------------------------------------------------------------------------
// Rotary applied in-place to g_q and g_k.
// ---------------------------------------------------------------------------
__global__ __launch_bounds__(256) void rotary_kernel(const float* __restrict__ cosb,
                                                     const float* __restrict__ sinb)
{
    int idx = blockIdx.x * blockDim.x + threadIdx.x;   // over M_*H_*32
    int j  = idx & 31;
    int h  = (idx >> 5) & 15;
    int ms = idx >> 9;                 // b*S + s
    int s  = ms & (S_ - 1);

    float c1 = cosb[s*HD_ + j],      s1 = sinb[s*HD_ + j];
    float c2 = cosb[s*HD_ + j + 32], s2 = sinb[s*HD_ + j + 32];

    size_t base = (size_t)ms * D_ + h * HD_;
    float q1 = g_q[base + j], q2 = g_q[base + j + 32];
    g_q[base + j]      = q1 * c1 - q2 * s1;
    g_q[base + j + 32] = q2 * c2 + q1 * s2;
    float k1 = g_k[base + j], k2 = g_k[base + j + 32];
    g_k[base + j]      = k1 * c1 - k2 * s1;
    g_k[base + j + 32] = k2 * c2 + k1 * s2;
}

// ---------------------------------------------------------------------------
// Flash attention, causal. Block = (b,h) x 64-query tile. 256 threads.
// Qs/Ks stored [d][m] (stride 68 for conflict-free transposed stores),
// K buffer reused for P[i][j]; V stored naturally [j][d] stride 64.
// ---------------------------------------------------------------------------
#define QS_STRIDE 68
#define SMEM_FLOATS (64*QS_STRIDE*2 + 64*64)

__global__ __launch_bounds__(256) void attn_kernel()
{
    extern __shared__ float sm[];
    float* Qs  = sm;                       // [64][68], layout [d][i]
    float* KPs = sm + 64 * QS_STRIDE;      // K: [d][j] ; then P: [i][j]
    float* Vs  = sm + 2 * 64 * QS_STRIDE;  // [j][d], stride 64

    const int bh = blockIdx.x;
    const int b  = bh >> 4;
    const int h  = bh & 15;
    const int qt = blockIdx.y;
    const int q0 = qt * 64;

    const int tid = threadIdx.x;
    const int tx  = tid & 15;
    const int ty  = tid >> 4;

    // Load Q tile (transposed into Qs[d][i])
    #pragma unroll
    for (int it = 0; it < 4; it++) {
        int l  = tid + it * 256;
        int i  = l >> 4;
        int d4 = (l & 15) * 4;
        float4 qv = *(const float4*)&g_q[(size_t)(b*S_ + q0 + i) * D_ + h*HD_ + d4];
        Qs[(d4+0)*QS_STRIDE + i] = qv.x;
        Qs[(d4+1)*QS_STRIDE + i] = qv.y;
        Qs[(d4+2)*QS_STRIDE + i] = qv.z;
        Qs[(d4+3)*QS_STRIDE + i] = qv.w;
    }

    const float NEG_INF = __int_as_float(0xff800000);
    float m_i[4], l_i[4], o[4][4];
    #pragma unroll
    for (int i = 0; i < 4; i++) {
        m_i[i] = NEG_INF; l_i[i] = 0.f;
        #pragma unroll
        for (int j = 0; j < 4; j++) o[i][j] = 0.f;
    }

    for (int kt = 0; kt <= qt; kt++) {
        const int k0 = kt * 64;
        __syncthreads();   // protect KPs/Vs reuse from previous iteration

        #pragma unroll
        for (int it = 0; it < 4; it++) {
            int l  = tid + it * 256;
            int j  = l >> 4;
            int d4 = (l & 15) * 4;
            size_t goff = (size_t)(b*S_ + k0 + j) * D_ + h*HD_ + d4;
            float4 kv = *(const float4*)&g_k[goff];
            KPs[(d4+0)*QS_STRIDE + j] = kv.x;
            KPs[(d4+1)*QS_STRIDE + j] = kv.y;
            KPs[(d4+2)*QS_STRIDE + j] = kv.z;
            KPs[(d4+3)*QS_STRIDE + j] = kv.w;
            *(float4*)&Vs[j*64 + d4] = *(const float4*)&g_v[goff];
        }
        __syncthreads();

        // S = Q K^T
        float s[4][4];
        #pragma unroll
        for (int i = 0; i < 4; i++)
            #pragma unroll
            for (int j = 0; j < 4; j++) s[i][j] = 0.f;
        #pragma unroll 8
        for (int d = 0; d < 64; d++) {
            float4 qv = *(const float4*)&Qs[d*QS_STRIDE + ty*4];
            float4 kv = *(const float4*)&KPs[d*QS_STRIDE + tx*4];
            float a[4] = {qv.x, qv.y, qv.z, qv.w};
            float bb[4] = {kv.x, kv.y, kv.z, kv.w};
            #pragma unroll
            for (int i = 0; i < 4; i++)
                #pragma unroll
                for (int j = 0; j < 4; j++)
                    s[i][j] = fmaf(a[i], bb[j], s[i][j]);
        }

        // scale + causal mask (only diagonal tile needs masking)
        const float scale = 0.125f;
        #pragma unroll
        for (int i = 0; i < 4; i++)
            #pragma unroll
            for (int j = 0; j < 4; j++) s[i][j] *= scale;
        if (kt == qt) {
            #pragma unroll
            for (int i = 0; i < 4; i++)
                #pragma unroll
                for (int j = 0; j < 4; j++)
                    if (tx*4 + j > ty*4 + i) s[i][j] = NEG_INF;
        }

        // online softmax + rescale accumulators
        float p[4][4];
        #pragma unroll
        for (int i = 0; i < 4; i++) {
            float mx = fmaxf(fmaxf(s[i][0], s[i][1]), fmaxf(s[i][2], s[i][3]));
            #pragma unroll
            for (int off = 8; off; off >>= 1)
                mx = fmaxf(mx, __shfl_xor_sync(0xffffffffu, mx, off));
            float mnew = fmaxf(m_i[i], mx);
            float r = __expf(m_i[i] - mnew);
            float sum = 0.f;
            #pragma unroll
            for (int j = 0; j < 4; j++) {
                p[i][j] = __expf(s[i][j] - mnew);
                sum += p[i][j];
            }
            #pragma unroll
            for (int off = 8; off; off >>= 1)
                sum += __shfl_xor_sync(0xffffffffu, sum, off);
            l_i[i] = l_i[i] * r + sum;
            m_i[i] = mnew;
            #pragma unroll
            for (int j = 0; j < 4; j++) o[i][j] *= r;
        }

        __syncthreads();  // everyone done reading K from KPs
        #pragma unroll
        for (int i = 0; i < 4; i++) {
            float4 pv = make_float4(p[i][0], p[i][1], p[i][2], p[i][3]);
            *(float4*)&KPs[(ty*4 + i)*QS_STRIDE + tx*4] = pv;
        }
        __syncthreads();

        // O += P V
        #pragma unroll 8
        for (int j = 0; j < 64; j++) {
            float4 vv = *(const float4*)&Vs[j*64 + tx*4];
            #pragma unroll
            for (int i = 0; i < 4; i++) {
                float pp = KPs[(ty*4 + i)*QS_STRIDE + j];
                o[i][0] = fmaf(pp, vv.x, o[i][0]);
                o[i][1] = fmaf(pp, vv.y, o[i][1]);
                o[i][2] = fmaf(pp, vv.z, o[i][2]);
                o[i][3] = fmaf(pp, vv.w, o[i][3]);
            }
        }
    }

    // epilogue: normalize and write ctx in [b, s, h, d] layout
    #pragma unroll
    for (int i = 0; i < 4; i++) {
        float inv = 1.f / l_i[i];
        float4 r;
        r.x = o[i][0] * inv; r.y = o[i][1] * inv;
        r.z = o[i][2] * inv; r.w = o[i][3] * inv;
        *(float4*)&g_ctx[(size_t)(b*S_ + q0 + ty*4 + i) * D_ + h*HD_ + tx*4] = r;
    }
}

// ---------------------------------------------------------------------------
extern "C" void kernel_launch(void* const* d_in, const int* in_sizes, int n_in,
                              void* d_out, int out_size)
{
    const float* x    = (const float*)d_in[0];
    const float* cosb = (const float*)d_in[1];
    const float* sinb = (const float*)d_in[2];
    // d_in[3] = attn_mask (causal; implemented analytically)
    const float* Wq = (const float*)d_in[4];
    const float* bq = (const float*)d_in[5];
    const float* Wk = (const float*)d_in[6];
    const float* bk = (const float*)d_in[7];
    const float* Wv = (const float*)d_in[8];
    const float* bv = (const float*)d_in[9];
    const float* Wo = (const float*)d_in[10];
    const float* bo = (const float*)d_in[11];
    float* out = (float*)d_out;

    float *q, *k, *v, *ctx;
    cudaGetSymbolAddress((void**)&q,   g_q);
    cudaGetSymbolAddress((void**)&k,   g_k);
    cudaGetSymbolAddress((void**)&v,   g_v);
    cudaGetSymbolAddress((void**)&ctx, g_ctx);

    dim3 gg(D_/128, M_/128);   // (8, 64)
    gemm_nt<<<gg, 256>>>(x, Wq, bq, q);
    gemm_nt<<<gg, 256>>>(x, Wk, bk, k);
    gemm_nt<<<gg, 256>>>(x, Wv, bv, v);

    rotary_kernel<<<(M_*H_*32)/256, 256>>>(cosb, sinb);

    cudaFuncSetAttribute(attn_kernel,
                         cudaFuncAttributeMaxDynamicSharedMemorySize,
                         SMEM_FLOATS * sizeof(float));
    attn_kernel<<<dim3(B_*H_, S_/64), 256, SMEM_FLOATS * sizeof(float)>>>();

    gemm_nt<<<gg, 256>>>(ctx, Wo, bo, out);
}

// round 5
// speedup vs baseline: 1.6822x; 1.6822x over previous
#include <cuda_runtime.h>
#include <math.h>

#define B_  4
#define S_  2048
#define D_  1024
#define H_  16
#define HD_ 64
#define M_  (B_*S_)

// Scratch (allocation-free rule: __device__ globals)
__device__ float g_q[M_*D_];
__device__ float g_k[M_*D_];
__device__ float g_v[M_*D_];
__device__ float g_ctx[M_*D_];

// ---------------------------------------------------------------------------
// TF32 tensor-core GEMM: out[m,n] = sum_k A[m,k]*W[n,k] + bias[n]
// M=8192, N=K=1024. 128x128 block tile, BK=16, 256 threads (8 warps).
// Warp tile 64x32 -> 4 m-frags x 4 n-frags of m16n8k8.
// Smem row stride 20 floats => fragment LDS is bank-conflict-free.
// ---------------------------------------------------------------------------
#define BK_   16
#define SSTR  20

__device__ __forceinline__ float f2tf32(float f) {
    unsigned u;
    asm("cvt.rna.tf32.f32 %0, %1;" : "=r"(u) : "f"(f));
    return __uint_as_float(u);
}

__global__ __launch_bounds__(256) void gemm_tf32(const float* __restrict__ A,
                                                 const float* __restrict__ W,
                                                 const float* __restrict__ bias,
                                                 float* __restrict__ out)
{
    __shared__ float As[128 * SSTR];
    __shared__ float Bs[128 * SSTR];

    const int tid  = threadIdx.x;
    const int warp = tid >> 5;
    const int lane = tid & 31;
    const int g    = lane >> 2;      // groupID 0..7
    const int t    = lane & 3;       // threadID_in_group 0..3
    const int wm   = warp & 1;       // 0..1 : 64 rows
    const int wn   = warp >> 1;      // 0..3 : 32 cols

    const int lr = tid >> 2;         // 0..63 (and +64)
    const int lc = (tid & 3) * 4;    // 0,4,8,12

    const float* Ap = A + (size_t)(blockIdx.y * 128 + lr) * D_ + lc;
    const float* Wp = W + (size_t)(blockIdx.x * 128 + lr) * D_ + lc;

    float acc[4][4][4];
    #pragma unroll
    for (int i = 0; i < 4; i++)
        #pragma unroll
        for (int j = 0; j < 4; j++)
            #pragma unroll
            for (int r = 0; r < 4; r++) acc[i][j][r] = 0.f;

    // preload first k-tile into registers
    float4 a0v = *(const float4*)(Ap);
    float4 a1v = *(const float4*)(Ap + (size_t)64 * D_);
    float4 b0v = *(const float4*)(Wp);
    float4 b1v = *(const float4*)(Wp + (size_t)64 * D_);

    for (int k0 = 0; k0 < D_; k0 += BK_) {
        __syncthreads();   // previous compute finished reading smem
        float4 ca0 = make_float4(f2tf32(a0v.x), f2tf32(a0v.y), f2tf32(a0v.z), f2tf32(a0v.w));
        float4 ca1 = make_float4(f2tf32(a1v.x), f2tf32(a1v.y), f2tf32(a1v.z), f2tf32(a1v.w));
        float4 cb0 = make_float4(f2tf32(b0v.x), f2tf32(b0v.y), f2tf32(b0v.z), f2tf32(b0v.w));
        float4 cb1 = make_float4(f2tf32(b1v.x), f2tf32(b1v.y), f2tf32(b1v.z), f2tf32(b1v.w));
        *(float4*)&As[lr * SSTR + lc]        = ca0;
        *(float4*)&As[(lr + 64) * SSTR + lc] = ca1;
        *(float4*)&Bs[lr * SSTR + lc]        = cb0;
        *(float4*)&Bs[(lr + 64) * SSTR + lc] = cb1;
        __syncthreads();

        if (k0 + BK_ < D_) {
            a0v = *(const float4*)(Ap + k0 + BK_);
            a1v = *(const float4*)(Ap + (size_t)64 * D_ + k0 + BK_);
            b0v = *(const float4*)(Wp + k0 + BK_);
            b1v = *(const float4*)(Wp + (size_t)64 * D_ + k0 + BK_);
        }

        #pragma unroll
        for (int ks = 0; ks < 2; ks++) {
            const int kk = ks * 8;
            unsigned af[4][4], bf[4][2];
            #pragma unroll
            for (int fm = 0; fm < 4; fm++) {
                const int rb = wm * 64 + fm * 16;
                af[fm][0] = __float_as_uint(As[(rb + g)     * SSTR + kk + t]);
                af[fm][1] = __float_as_uint(As[(rb + g + 8) * SSTR + kk + t]);
                af[fm][2] = __float_as_uint(As[(rb + g)     * SSTR + kk + t + 4]);
                af[fm][3] = __float_as_uint(As[(rb + g + 8) * SSTR + kk + t + 4]);
            }
            #pragma unroll
            for (int fn = 0; fn < 4; fn++) {
                const int nb = wn * 32 + fn * 8;
                bf[fn][0] = __float_as_uint(Bs[(nb + g) * SSTR + kk + t]);
                bf[fn][1] = __float_as_uint(Bs[(nb + g) * SSTR + kk + t + 4]);
            }
            #pragma unroll
            for (int fm = 0; fm < 4; fm++)
                #pragma unroll
                for (int fn = 0; fn < 4; fn++) {
                    asm volatile(
                        "mma.sync.aligned.m16n8k8.row.col.f32.tf32.tf32.f32 "
                        "{%0,%1,%2,%3}, {%4,%5,%6,%7}, {%8,%9}, {%0,%1,%2,%3};"
                        : "+f"(acc[fm][fn][0]), "+f"(acc[fm][fn][1]),
                          "+f"(acc[fm][fn][2]), "+f"(acc[fm][fn][3])
                        : "r"(af[fm][0]), "r"(af[fm][1]), "r"(af[fm][2]), "r"(af[fm][3]),
                          "r"(bf[fn][0]), "r"(bf[fn][1]));
                }
        }
    }

    // epilogue: c0=(g,2t) c1=(g,2t+1) c2=(g+8,2t) c3=(g+8,2t+1)
    #pragma unroll
    for (int fm = 0; fm < 4; fm++) {
        const int row = blockIdx.y * 128 + wm * 64 + fm * 16 + g;
        #pragma unroll
        for (int fn = 0; fn < 4; fn++) {
            const int col = blockIdx.x * 128 + wn * 32 + fn * 8 + 2 * t;
            const float bx = bias[col];
            const float by = bias[col + 1];
            float2 r0 = make_float2(acc[fm][fn][0] + bx, acc[fm][fn][1] + by);
            float2 r1 = make_float2(acc[fm][fn][2] + bx, acc[fm][fn][3] + by);
            *(float2*)&out[(size_t)row * D_ + col]        = r0;
            *(float2*)&out[(size_t)(row + 8) * D_ + col]  = r1;
        }
    }
}

// ---------------------------------------------------------------------------
// Rotary applied in-place to g_q and g_k.
// ---------------------------------------------------------------------------
__global__ __launch_bounds__(256) void rotary_kernel(const float* __restrict__ cosb,
                                                     const float* __restrict__ sinb)
{
    int idx = blockIdx.x * blockDim.x + threadIdx.x;   // over M_*H_*32
    int j  = idx & 31;
    int h  = (idx >> 5) & 15;
    int ms = idx >> 9;                 // b*S + s
    int s  = ms & (S_ - 1);

    float c1 = cosb[s*HD_ + j],      s1 = sinb[s*HD_ + j];
    float c2 = cosb[s*HD_ + j + 32], s2 = sinb[s*HD_ + j + 32];

    size_t base = (size_t)ms * D_ + h * HD_;
    float q1 = g_q[base + j], q2 = g_q[base + j + 32];
    g_q[base + j]      = q1 * c1 - q2 * s1;
    g_q[base + j + 32] = q2 * c2 + q1 * s2;
    float k1 = g_k[base + j], k2 = g_k[base + j + 32];
    g_k[base + j]      = k1 * c1 - k2 * s1;
    g_k[base + j + 32] = k2 * c2 + k1 * s2;
}

// ---------------------------------------------------------------------------
// Flash attention, causal. Block = (b,h) x 64-query tile. 256 threads. (fp32)
// ---------------------------------------------------------------------------
#define QS_STRIDE 68
#define SMEM_FLOATS (64*QS_STRIDE*2 + 64*64)

__global__ __launch_bounds__(256) void attn_kernel()
{
    extern __shared__ float sm[];
    float* Qs  = sm;                       // [64][68], layout [d][i]
    float* KPs = sm + 64 * QS_STRIDE;      // K: [d][j] ; then P: [i][j]
    float* Vs  = sm + 2 * 64 * QS_STRIDE;  // [j][d], stride 64

    const int bh = blockIdx.x;
    const int b  = bh >> 4;
    const int h  = bh & 15;
    const int qt = blockIdx.y;
    const int q0 = qt * 64;

    const int tid = threadIdx.x;
    const int tx  = tid & 15;
    const int ty  = tid >> 4;

    #pragma unroll
    for (int it = 0; it < 4; it++) {
        int l  = tid + it * 256;
        int i  = l >> 4;
        int d4 = (l & 15) * 4;
        float4 qv = *(const float4*)&g_q[(size_t)(b*S_ + q0 + i) * D_ + h*HD_ + d4];
        Qs[(d4+0)*QS_STRIDE + i] = qv.x;
        Qs[(d4+1)*QS_STRIDE + i] = qv.y;
        Qs[(d4+2)*QS_STRIDE + i] = qv.z;
        Qs[(d4+3)*QS_STRIDE + i] = qv.w;
    }

    const float NEG_INF = __int_as_float(0xff800000);
    float m_i[4], l_i[4], o[4][4];
    #pragma unroll
    for (int i = 0; i < 4; i++) {
        m_i[i] = NEG_INF; l_i[i] = 0.f;
        #pragma unroll
        for (int j = 0; j < 4; j++) o[i][j] = 0.f;
    }

    for (int kt = 0; kt <= qt; kt++) {
        const int k0 = kt * 64;
        __syncthreads();

        #pragma unroll
        for (int it = 0; it < 4; it++) {
            int l  = tid + it * 256;
            int j  = l >> 4;
            int d4 = (l & 15) * 4;
            size_t goff = (size_t)(b*S_ + k0 + j) * D_ + h*HD_ + d4;
            float4 kv = *(const float4*)&g_k[goff];
            KPs[(d4+0)*QS_STRIDE + j] = kv.x;
            KPs[(d4+1)*QS_STRIDE + j] = kv.y;
            KPs[(d4+2)*QS_STRIDE + j] = kv.z;
            KPs[(d4+3)*QS_STRIDE + j] = kv.w;
            *(float4*)&Vs[j*64 + d4] = *(const float4*)&g_v[goff];
        }
        __syncthreads();

        float s[4][4];
        #pragma unroll
        for (int i = 0; i < 4; i++)
            #pragma unroll
            for (int j = 0; j < 4; j++) s[i][j] = 0.f;
        #pragma unroll 8
        for (int d = 0; d < 64; d++) {
            float4 qv = *(const float4*)&Qs[d*QS_STRIDE + ty*4];
            float4 kv = *(const float4*)&KPs[d*QS_STRIDE + tx*4];
            float a[4] = {qv.x, qv.y, qv.z, qv.w};
            float bb[4] = {kv.x, kv.y, kv.z, kv.w};
            #pragma unroll
            for (int i = 0; i < 4; i++)
                #pragma unroll
                for (int j = 0; j < 4; j++)
                    s[i][j] = fmaf(a[i], bb[j], s[i][j]);
        }

        const float scale = 0.125f;
        #pragma unroll
        for (int i = 0; i < 4; i++)
            #pragma unroll
            for (int j = 0; j < 4; j++) s[i][j] *= scale;
        if (kt == qt) {
            #pragma unroll
            for (int i = 0; i < 4; i++)
                #pragma unroll
                for (int j = 0; j < 4; j++)
                    if (tx*4 + j > ty*4 + i) s[i][j] = NEG_INF;
        }

        float p[4][4];
        #pragma unroll
        for (int i = 0; i < 4; i++) {
            float mx = fmaxf(fmaxf(s[i][0], s[i][1]), fmaxf(s[i][2], s[i][3]));
            #pragma unroll
            for (int off = 8; off; off >>= 1)
                mx = fmaxf(mx, __shfl_xor_sync(0xffffffffu, mx, off));
            float mnew = fmaxf(m_i[i], mx);
            float r = __expf(m_i[i] - mnew);
            float sum = 0.f;
            #pragma unroll
            for (int j = 0; j < 4; j++) {
                p[i][j] = __expf(s[i][j] - mnew);
                sum += p[i][j];
            }
            #pragma unroll
            for (int off = 8; off; off >>= 1)
                sum += __shfl_xor_sync(0xffffffffu, sum, off);
            l_i[i] = l_i[i] * r + sum;
            m_i[i] = mnew;
            #pragma unroll
            for (int j = 0; j < 4; j++) o[i][j] *= r;
        }

        __syncthreads();
        #pragma unroll
        for (int i = 0; i < 4; i++) {
            float4 pv = make_float4(p[i][0], p[i][1], p[i][2], p[i][3]);
            *(float4*)&KPs[(ty*4 + i)*QS_STRIDE + tx*4] = pv;
        }
        __syncthreads();

        #pragma unroll 8
        for (int j = 0; j < 64; j++) {
            float4 vv = *(const float4*)&Vs[j*64 + tx*4];
            #pragma unroll
            for (int i = 0; i < 4; i++) {
                float pp = KPs[(ty*4 + i)*QS_STRIDE + j];
                o[i][0] = fmaf(pp, vv.x, o[i][0]);
                o[i][1] = fmaf(pp, vv.y, o[i][1]);
                o[i][2] = fmaf(pp, vv.z, o[i][2]);
                o[i][3] = fmaf(pp, vv.w, o[i][3]);
            }
        }
    }

    #pragma unroll
    for (int i = 0; i < 4; i++) {
        float inv = 1.f / l_i[i];
        float4 r;
        r.x = o[i][0] * inv; r.y = o[i][1] * inv;
        r.z = o[i][2] * inv; r.w = o[i][3] * inv;
        *(float4*)&g_ctx[(size_t)(b*S_ + q0 + ty*4 + i) * D_ + h*HD_ + tx*4] = r;
    }
}

// ---------------------------------------------------------------------------
extern "C" void kernel_launch(void* const* d_in, const int* in_sizes, int n_in,
                              void* d_out, int out_size)
{
    const float* x    = (const float*)d_in[0];
    const float* cosb = (const float*)d_in[1];
    const float* sinb = (const float*)d_in[2];
    // d_in[3] = attn_mask (causal; implemented analytically)
    const float* Wq = (const float*)d_in[4];
    const float* bq = (const float*)d_in[5];
    const float* Wk = (const float*)d_in[6];
    const float* bk = (const float*)d_in[7];
    const float* Wv = (const float*)d_in[8];
    const float* bv = (const float*)d_in[9];
    const float* Wo = (const float*)d_in[10];
    const float* bo = (const float*)d_in[11];
    float* out = (float*)d_out;

    float *q, *k, *v, *ctx;
    cudaGetSymbolAddress((void**)&q,   g_q);
    cudaGetSymbolAddress((void**)&k,   g_k);
    cudaGetSymbolAddress((void**)&v,   g_v);
    cudaGetSymbolAddress((void**)&ctx, g_ctx);

    dim3 gg(D_/128, M_/128);   // (8, 64)
    gemm_tf32<<<gg, 256>>>(x, Wq, bq, q);
    gemm_tf32<<<gg, 256>>>(x, Wk, bk, k);
    gemm_tf32<<<gg, 256>>>(x, Wv, bv, v);

    rotary_kernel<<<(M_*H_*32)/256, 256>>>(cosb, sinb);

    cudaFuncSetAttribute(attn_kernel,
                         cudaFuncAttributeMaxDynamicSharedMemorySize,
                         SMEM_FLOATS * sizeof(float));
    attn_kernel<<<dim3(B_*H_, S_/64), 256, SMEM_FLOATS * sizeof(float)>>>();

    gemm_tf32<<<gg, 256>>>(ctx, Wo, bo, out);
}

// round 6
// speedup vs baseline: 1.7885x; 1.0632x over previous
#include <cuda_runtime.h>
#include <math.h>

#define B_  4
#define S_  2048
#define D_  1024
#define H_  16
#define HD_ 64
#define M_  (B_*S_)

// Scratch (allocation-free rule: __device__ globals)
__device__ float g_q[M_*D_];
__device__ float g_k[M_*D_];
__device__ float g_v[M_*D_];
__device__ float g_ctx[M_*D_];

__device__ __forceinline__ unsigned tf32u(float f) {
    unsigned u;
    asm("cvt.rna.tf32.f32 %0, %1;" : "=r"(u) : "f"(f));
    return u;
}
__device__ __forceinline__ float tf32f(float f) { return __uint_as_float(tf32u(f)); }

__device__ __forceinline__ void mma_tf32(float* c,
                                         unsigned a0, unsigned a1, unsigned a2, unsigned a3,
                                         unsigned b0, unsigned b1)
{
    asm volatile(
        "mma.sync.aligned.m16n8k8.row.col.f32.tf32.tf32.f32 "
        "{%0,%1,%2,%3}, {%4,%5,%6,%7}, {%8,%9}, {%0,%1,%2,%3};"
        : "+f"(c[0]), "+f"(c[1]), "+f"(c[2]), "+f"(c[3])
        : "r"(a0), "r"(a1), "r"(a2), "r"(a3), "r"(b0), "r"(b1));
}

// ---------------------------------------------------------------------------
// TF32 tensor-core GEMM: out[m,n] = sum_k A[m,k]*W[n,k] + bias[n]
// (unchanged from round 5 — measured 166us each)
// ---------------------------------------------------------------------------
#define BK_   16
#define SSTR  20

__global__ __launch_bounds__(256) void gemm_tf32(const float* __restrict__ A,
                                                 const float* __restrict__ W,
                                                 const float* __restrict__ bias,
                                                 float* __restrict__ out)
{
    __shared__ float As[128 * SSTR];
    __shared__ float Bs[128 * SSTR];

    const int tid  = threadIdx.x;
    const int warp = tid >> 5;
    const int lane = tid & 31;
    const int g    = lane >> 2;
    const int t    = lane & 3;
    const int wm   = warp & 1;
    const int wn   = warp >> 1;

    const int lr = tid >> 2;
    const int lc = (tid & 3) * 4;

    const float* Ap = A + (size_t)(blockIdx.y * 128 + lr) * D_ + lc;
    const float* Wp = W + (size_t)(blockIdx.x * 128 + lr) * D_ + lc;

    float acc[4][4][4];
    #pragma unroll
    for (int i = 0; i < 4; i++)
        #pragma unroll
        for (int j = 0; j < 4; j++)
            #pragma unroll
            for (int r = 0; r < 4; r++) acc[i][j][r] = 0.f;

    float4 a0v = *(const float4*)(Ap);
    float4 a1v = *(const float4*)(Ap + (size_t)64 * D_);
    float4 b0v = *(const float4*)(Wp);
    float4 b1v = *(const float4*)(Wp + (size_t)64 * D_);

    for (int k0 = 0; k0 < D_; k0 += BK_) {
        __syncthreads();
        float4 ca0 = make_float4(tf32f(a0v.x), tf32f(a0v.y), tf32f(a0v.z), tf32f(a0v.w));
        float4 ca1 = make_float4(tf32f(a1v.x), tf32f(a1v.y), tf32f(a1v.z), tf32f(a1v.w));
        float4 cb0 = make_float4(tf32f(b0v.x), tf32f(b0v.y), tf32f(b0v.z), tf32f(b0v.w));
        float4 cb1 = make_float4(tf32f(b1v.x), tf32f(b1v.y), tf32f(b1v.z), tf32f(b1v.w));
        *(float4*)&As[lr * SSTR + lc]        = ca0;
        *(float4*)&As[(lr + 64) * SSTR + lc] = ca1;
        *(float4*)&Bs[lr * SSTR + lc]        = cb0;
        *(float4*)&Bs[(lr + 64) * SSTR + lc] = cb1;
        __syncthreads();

        if (k0 + BK_ < D_) {
            a0v = *(const float4*)(Ap + k0 + BK_);
            a1v = *(const float4*)(Ap + (size_t)64 * D_ + k0 + BK_);
            b0v = *(const float4*)(Wp + k0 + BK_);
            b1v = *(const float4*)(Wp + (size_t)64 * D_ + k0 + BK_);
        }

        #pragma unroll
        for (int ks = 0; ks < 2; ks++) {
            const int kk = ks * 8;
            unsigned af[4][4], bf[4][2];
            #pragma unroll
            for (int fm = 0; fm < 4; fm++) {
                const int rb = wm * 64 + fm * 16;
                af[fm][0] = __float_as_uint(As[(rb + g)     * SSTR + kk + t]);
                af[fm][1] = __float_as_uint(As[(rb + g + 8) * SSTR + kk + t]);
                af[fm][2] = __float_as_uint(As[(rb + g)     * SSTR + kk + t + 4]);
                af[fm][3] = __float_as_uint(As[(rb + g + 8) * SSTR + kk + t + 4]);
            }
            #pragma unroll
            for (int fn = 0; fn < 4; fn++) {
                const int nb = wn * 32 + fn * 8;
                bf[fn][0] = __float_as_uint(Bs[(nb + g) * SSTR + kk + t]);
                bf[fn][1] = __float_as_uint(Bs[(nb + g) * SSTR + kk + t + 4]);
            }
            #pragma unroll
            for (int fm = 0; fm < 4; fm++)
                #pragma unroll
                for (int fn = 0; fn < 4; fn++)
                    mma_tf32(acc[fm][fn], af[fm][0], af[fm][1], af[fm][2], af[fm][3],
                             bf[fn][0], bf[fn][1]);
        }
    }

    #pragma unroll
    for (int fm = 0; fm < 4; fm++) {
        const int row = blockIdx.y * 128 + wm * 64 + fm * 16 + g;
        #pragma unroll
        for (int fn = 0; fn < 4; fn++) {
            const int col = blockIdx.x * 128 + wn * 32 + fn * 8 + 2 * t;
            const float bx = bias[col];
            const float by = bias[col + 1];
            float2 r0 = make_float2(acc[fm][fn][0] + bx, acc[fm][fn][1] + by);
            float2 r1 = make_float2(acc[fm][fn][2] + bx, acc[fm][fn][3] + by);
            *(float2*)&out[(size_t)row * D_ + col]       = r0;
            *(float2*)&out[(size_t)(row + 8) * D_ + col] = r1;
        }
    }
}

// ---------------------------------------------------------------------------
// Rotary applied in-place to g_q and g_k.
// ---------------------------------------------------------------------------
__global__ __launch_bounds__(256) void rotary_kernel(const float* __restrict__ cosb,
                                                     const float* __restrict__ sinb)
{
    int idx = blockIdx.x * blockDim.x + threadIdx.x;
    int j  = idx & 31;
    int h  = (idx >> 5) & 15;
    int ms = idx >> 9;
    int s  = ms & (S_ - 1);

    float c1 = cosb[s*HD_ + j],      s1 = sinb[s*HD_ + j];
    float c2 = cosb[s*HD_ + j + 32], s2 = sinb[s*HD_ + j + 32];

    size_t base = (size_t)ms * D_ + h * HD_;
    float q1 = g_q[base + j], q2 = g_q[base + j + 32];
    g_q[base + j]      = q1 * c1 - q2 * s1;
    g_q[base + j + 32] = q2 * c2 + q1 * s2;
    float k1 = g_k[base + j], k2 = g_k[base + j + 32];
    g_k[base + j]      = k1 * c1 - k2 * s1;
    g_k[base + j + 32] = k2 * c2 + k1 * s2;
}

// ---------------------------------------------------------------------------
// Tensor-core flash attention (tf32), causal.
// Block = (b,h) x 128-query tile, 256 threads (8 warps x 16 rows).
// Q fragments persist in registers; Q smem buffer reused for P (warp-private
// rows). K stored [j][d], V stored [j][d]; stride 76 (=12 mod 32) makes all
// fragment LDS patterns bank-conflict-free. Scale 1/8 folded into Q convert.
// ---------------------------------------------------------------------------
#define TSTR 76
#define ATT_SMEM_BYTES ((128*TSTR + 64*TSTR + 64*TSTR) * 4)

__global__ __launch_bounds__(256) void attn_tc()
{
    extern __shared__ float sm[];
    float* QPs = sm;                  // [128][TSTR] : Q tile, then P tile
    float* Ks  = sm + 128 * TSTR;     // [64][TSTR]  : K[j][d]
    float* Vs  = Ks + 64 * TSTR;      // [64][TSTR]  : V[j][d]

    const int qt = (int)gridDim.x - 1 - (int)blockIdx.x;  // heavy tiles first
    const int bh = blockIdx.y;
    const int b  = bh >> 4;
    const int h  = bh & 15;
    const int q0 = qt * 128;

    const int tid  = threadIdx.x;
    const int warp = tid >> 5;
    const int lane = tid & 31;
    const int g    = lane >> 2;
    const int t    = lane & 3;
    const int rb   = warp * 16;

    // ---- load Q tile (scaled by 1/8, tf32-rounded), layout [i][d] ----
    #pragma unroll
    for (int it = 0; it < 8; it++) {
        int l  = tid + it * 256;
        int i  = l >> 4;
        int d4 = (l & 15) * 4;
        float4 qv = *(const float4*)&g_q[(size_t)(b*S_ + q0 + i) * D_ + h*HD_ + d4];
        float4 cv = make_float4(tf32f(qv.x * 0.125f), tf32f(qv.y * 0.125f),
                                tf32f(qv.z * 0.125f), tf32f(qv.w * 0.125f));
        *(float4*)&QPs[i * TSTR + d4] = cv;
    }
    __syncthreads();

    // ---- Q fragments -> registers (own 16 rows only) ----
    unsigned qa[8][4];
    #pragma unroll
    for (int ks = 0; ks < 8; ks++) {
        int kk = ks * 8;
        qa[ks][0] = __float_as_uint(QPs[(rb + g)     * TSTR + kk + t]);
        qa[ks][1] = __float_as_uint(QPs[(rb + g + 8) * TSTR + kk + t]);
        qa[ks][2] = __float_as_uint(QPs[(rb + g)     * TSTR + kk + t + 4]);
        qa[ks][3] = __float_as_uint(QPs[(rb + g + 8) * TSTR + kk + t + 4]);
    }
    // From here QPs rows [rb, rb+16) are warp-private (P buffer).

    float m_lo = -1e30f, m_hi = -1e30f, l_lo = 0.f, l_hi = 0.f;
    float oacc[8][4];
    #pragma unroll
    for (int nf = 0; nf < 8; nf++)
        #pragma unroll
        for (int r = 0; r < 4; r++) oacc[nf][r] = 0.f;

    const int nkt = 2 * qt + 2;
    for (int kt = 0; kt < nkt; kt++) {
        const int k0 = kt * 64;
        __syncthreads();   // all warps done with previous K/V (and P reads)

        // ---- load K,V tiles (tf32-rounded), layout [j][d] ----
        #pragma unroll
        for (int it = 0; it < 4; it++) {
            int l  = tid + it * 256;
            int j  = l >> 4;
            int d4 = (l & 15) * 4;
            size_t go = (size_t)(b*S_ + k0 + j) * D_ + h*HD_ + d4;
            float4 kv = *(const float4*)&g_k[go];
            float4 vv = *(const float4*)&g_v[go];
            *(float4*)&Ks[j * TSTR + d4] =
                make_float4(tf32f(kv.x), tf32f(kv.y), tf32f(kv.z), tf32f(kv.w));
            *(float4*)&Vs[j * TSTR + d4] =
                make_float4(tf32f(vv.x), tf32f(vv.y), tf32f(vv.z), tf32f(vv.w));
        }
        __syncthreads();

        // ---- S = (Q/8) K^T : 16x64 per warp ----
        float sacc[8][4];
        #pragma unroll
        for (int nf = 0; nf < 8; nf++)
            #pragma unroll
            for (int r = 0; r < 4; r++) sacc[nf][r] = 0.f;

        #pragma unroll
        for (int ks = 0; ks < 8; ks++) {
            int kk = ks * 8;
            #pragma unroll
            for (int nf = 0; nf < 8; nf++) {
                unsigned b0 = __float_as_uint(Ks[(nf*8 + g) * TSTR + kk + t]);
                unsigned b1 = __float_as_uint(Ks[(nf*8 + g) * TSTR + kk + t + 4]);
                mma_tf32(sacc[nf], qa[ks][0], qa[ks][1], qa[ks][2], qa[ks][3], b0, b1);
            }
        }

        // ---- causal mask (only last two k-tiles can cross the diagonal) ----
        if (kt >= nkt - 2) {
            const int rlo = q0 + rb + g;
            #pragma unroll
            for (int nf = 0; nf < 8; nf++) {
                int c0 = k0 + nf*8 + 2*t;
                int c1 = c0 + 1;
                if (c0 > rlo)     sacc[nf][0] = -1e30f;
                if (c1 > rlo)     sacc[nf][1] = -1e30f;
                if (c0 > rlo + 8) sacc[nf][2] = -1e30f;
                if (c1 > rlo + 8) sacc[nf][3] = -1e30f;
            }
        }

        // ---- online softmax (rows g and g+8; quad = lanes sharing g) ----
        float mx_lo = -1e30f, mx_hi = -1e30f;
        #pragma unroll
        for (int nf = 0; nf < 8; nf++) {
            mx_lo = fmaxf(mx_lo, fmaxf(sacc[nf][0], sacc[nf][1]));
            mx_hi = fmaxf(mx_hi, fmaxf(sacc[nf][2], sacc[nf][3]));
        }
        mx_lo = fmaxf(mx_lo, __shfl_xor_sync(0xffffffffu, mx_lo, 1));
        mx_lo = fmaxf(mx_lo, __shfl_xor_sync(0xffffffffu, mx_lo, 2));
        mx_hi = fmaxf(mx_hi, __shfl_xor_sync(0xffffffffu, mx_hi, 1));
        mx_hi = fmaxf(mx_hi, __shfl_xor_sync(0xffffffffu, mx_hi, 2));

        float mn_lo = fmaxf(m_lo, mx_lo);
        float mn_hi = fmaxf(m_hi, mx_hi);
        float r_lo  = __expf(m_lo - mn_lo);
        float r_hi  = __expf(m_hi - mn_hi);

        float sum_lo = 0.f, sum_hi = 0.f;
        #pragma unroll
        for (int nf = 0; nf < 8; nf++) {
            sacc[nf][0] = __expf(sacc[nf][0] - mn_lo);
            sacc[nf][1] = __expf(sacc[nf][1] - mn_lo);
            sacc[nf][2] = __expf(sacc[nf][2] - mn_hi);
            sacc[nf][3] = __expf(sacc[nf][3] - mn_hi);
            sum_lo += sacc[nf][0] + sacc[nf][1];
            sum_hi += sacc[nf][2] + sacc[nf][3];
        }
        sum_lo += __shfl_xor_sync(0xffffffffu, sum_lo, 1);
        sum_lo += __shfl_xor_sync(0xffffffffu, sum_lo, 2);
        sum_hi += __shfl_xor_sync(0xffffffffu, sum_hi, 1);
        sum_hi += __shfl_xor_sync(0xffffffffu, sum_hi, 2);

        l_lo = l_lo * r_lo + sum_lo;  m_lo = mn_lo;
        l_hi = l_hi * r_hi + sum_hi;  m_hi = mn_hi;

        #pragma unroll
        for (int nf = 0; nf < 8; nf++) {
            oacc[nf][0] *= r_lo;  oacc[nf][1] *= r_lo;
            oacc[nf][2] *= r_hi;  oacc[nf][3] *= r_hi;
        }

        // ---- store P (tf32) into warp-private rows of QPs ----
        #pragma unroll
        for (int nf = 0; nf < 8; nf++) {
            *(float2*)&QPs[(rb + g)     * TSTR + nf*8 + 2*t] =
                make_float2(tf32f(sacc[nf][0]), tf32f(sacc[nf][1]));
            *(float2*)&QPs[(rb + g + 8) * TSTR + nf*8 + 2*t] =
                make_float2(tf32f(sacc[nf][2]), tf32f(sacc[nf][3]));
        }
        __syncwarp();

        // ---- O += P V : A = P[16x64], B = V^T via Vs[k=j][n=d] ----
        #pragma unroll
        for (int ks = 0; ks < 8; ks++) {
            int kk = ks * 8;
            unsigned p0 = __float_as_uint(QPs[(rb + g)     * TSTR + kk + t]);
            unsigned p1 = __float_as_uint(QPs[(rb + g + 8) * TSTR + kk + t]);
            unsigned p2 = __float_as_uint(QPs[(rb + g)     * TSTR + kk + t + 4]);
            unsigned p3 = __float_as_uint(QPs[(rb + g + 8) * TSTR + kk + t + 4]);
            #pragma unroll
            for (int nf = 0; nf < 8; nf++) {
                unsigned b0 = __float_as_uint(Vs[(kk + t)     * TSTR + nf*8 + g]);
                unsigned b1 = __float_as_uint(Vs[(kk + t + 4) * TSTR + nf*8 + g]);
                mma_tf32(oacc[nf], p0, p1, p2, p3, b0, b1);
            }
        }
    }

    // ---- epilogue: normalize, write ctx in [b, s, h, d] layout ----
    const float inv_lo = 1.f / l_lo;
    const float inv_hi = 1.f / l_hi;
    #pragma unroll
    for (int nf = 0; nf < 8; nf++) {
        size_t off = (size_t)(b*S_ + q0 + rb + g) * D_ + h*HD_ + nf*8 + 2*t;
        *(float2*)&g_ctx[off] =
            make_float2(oacc[nf][0] * inv_lo, oacc[nf][1] * inv_lo);
        *(float2*)&g_ctx[off + (size_t)8 * D_] =
            make_float2(oacc[nf][2] * inv_hi, oacc[nf][3] * inv_hi);
    }
}

// ---------------------------------------------------------------------------
extern "C" void kernel_launch(void* const* d_in, const int* in_sizes, int n_in,
                              void* d_out, int out_size)
{
    const float* x    = (const float*)d_in[0];
    const float* cosb = (const float*)d_in[1];
    const float* sinb = (const float*)d_in[2];
    // d_in[3] = attn_mask (causal; implemented analytically)
    const float* Wq = (const float*)d_in[4];
    const float* bq = (const float*)d_in[5];
    const float* Wk = (const float*)d_in[6];
    const float* bk = (const float*)d_in[7];
    const float* Wv = (const float*)d_in[8];
    const float* bv = (const float*)d_in[9];
    const float* Wo = (const float*)d_in[10];
    const float* bo = (const float*)d_in[11];
    float* out = (float*)d_out;

    float *q, *k, *v, *ctx;
    cudaGetSymbolAddress((void**)&q,   g_q);
    cudaGetSymbolAddress((void**)&k,   g_k);
    cudaGetSymbolAddress((void**)&v,   g_v);
    cudaGetSymbolAddress((void**)&ctx, g_ctx);

    dim3 gg(D_/128, M_/128);   // (8, 64)
    gemm_tf32<<<gg, 256>>>(x, Wq, bq, q);
    gemm_tf32<<<gg, 256>>>(x, Wk, bk, k);
    gemm_tf32<<<gg, 256>>>(x, Wv, bv, v);

    rotary_kernel<<<(M_*H_*32)/256, 256>>>(cosb, sinb);

    cudaFuncSetAttribute(attn_tc,
                         cudaFuncAttributeMaxDynamicSharedMemorySize,
                         ATT_SMEM_BYTES);
    attn_tc<<<dim3(S_/128, B_*H_), 256, ATT_SMEM_BYTES>>>();

    gemm_tf32<<<gg, 256>>>(ctx, Wo, bo, out);
}

// round 7
// speedup vs baseline: 2.8137x; 1.5732x over previous
#include <cuda_runtime.h>
#include <math.h>

#define B_  4
#define S_  2048
#define D_  1024
#define H_  16
#define HD_ 64
#define M_  (B_*S_)

__device__ float g_q[M_*D_];
__device__ float g_k[M_*D_];
__device__ float g_v[M_*D_];
__device__ float g_ctx[M_*D_];

__device__ __forceinline__ unsigned tf32u(float f) {
    unsigned u;
    asm("cvt.rna.tf32.f32 %0, %1;" : "=r"(u) : "f"(f));
    return u;
}
__device__ __forceinline__ float tf32f(float f) { return __uint_as_float(tf32u(f)); }

__device__ __forceinline__ void mma_tf32(float* c,
                                         unsigned a0, unsigned a1, unsigned a2, unsigned a3,
                                         unsigned b0, unsigned b1)
{
    asm volatile(
        "mma.sync.aligned.m16n8k8.row.col.f32.tf32.tf32.f32 "
        "{%0,%1,%2,%3}, {%4,%5,%6,%7}, {%8,%9}, {%0,%1,%2,%3};"
        : "+f"(c[0]), "+f"(c[1]), "+f"(c[2]), "+f"(c[3])
        : "r"(a0), "r"(a1), "r"(a2), "r"(a3), "r"(b0), "r"(b1));
}

__device__ __forceinline__ void cpa16(unsigned saddr, const void* gptr) {
    asm volatile("cp.async.cg.shared.global [%0], [%1], 16;" :: "r"(saddr), "l"(gptr));
}
#define CP_COMMIT() asm volatile("cp.async.commit_group;")
#define CP_WAIT1()  asm volatile("cp.async.wait_group 1;")
#define CP_WAIT0()  asm volatile("cp.async.wait_group 0;")

// ---------------------------------------------------------------------------
// TF32 GEMM, cp.async double-buffered. out[m,n] = sum_k A[m,k]*W[n,k] + bias.
// 128x128 tile, BK=32, 256 threads, warp tile 64x32. Smem stride 36 (=4 mod 32
// -> conflict-free fragment LDS). tf32 cvt at fragment load.
// ---------------------------------------------------------------------------
#define GK   32
#define GSTR 36
#define GEMM_SMEM_BYTES (4 * 128 * GSTR * 4 * 2)   // As[2]+Bs[2]

__global__ __launch_bounds__(256) void gemm_tf32(const float* __restrict__ A,
                                                 const float* __restrict__ W,
                                                 const float* __restrict__ bias,
                                                 float* __restrict__ out)
{
    extern __shared__ float smg[];
    float* As = smg;                       // [2][128*GSTR]
    float* Bs = smg + 2 * 128 * GSTR;      // [2][128*GSTR]

    const int tid  = threadIdx.x;
    const int warp = tid >> 5;
    const int lane = tid & 31;
    const int g    = lane >> 2;
    const int t    = lane & 3;
    const int wm   = warp & 1;
    const int wn   = warp >> 1;

    const float* Abase = A + (size_t)(blockIdx.y * 128) * D_;
    const float* Wbase = W + (size_t)(blockIdx.x * 128) * D_;

    const unsigned sA = (unsigned)__cvta_generic_to_shared(As);
    const unsigned sB = (unsigned)__cvta_generic_to_shared(Bs);

    float acc[4][4][4];
    #pragma unroll
    for (int i = 0; i < 4; i++)
        #pragma unroll
        for (int j = 0; j < 4; j++)
            #pragma unroll
            for (int r = 0; r < 4; r++) acc[i][j][r] = 0.f;

    // issue one 128x32 tile pair into buffer `buf`
    auto issue = [&](int kt, int buf) {
        const int k0 = kt * GK;
        const unsigned bo = (unsigned)(buf * 128 * GSTR * 4);
        #pragma unroll
        for (int it = 0; it < 4; it++) {
            int idx = tid + it * 256;          // 0..1023
            int row = idx >> 3;                // 0..127
            int c4  = (idx & 7) * 4;           // 0..28
            unsigned so = bo + (unsigned)(row * GSTR + c4) * 4;
            cpa16(sA + so, Abase + (size_t)row * D_ + k0 + c4);
            cpa16(sB + so, Wbase + (size_t)row * D_ + k0 + c4);
        }
        CP_COMMIT();
    };

    issue(0, 0);
    const int NKT = D_ / GK;   // 32
    for (int kt = 0; kt < NKT; kt++) {
        const int buf = kt & 1;
        if (kt + 1 < NKT) { issue(kt + 1, (kt + 1) & 1); CP_WAIT1(); }
        else              { CP_WAIT0(); }
        __syncthreads();

        const float* Ab = As + buf * 128 * GSTR;
        const float* Bb = Bs + buf * 128 * GSTR;
        #pragma unroll
        for (int ks = 0; ks < 4; ks++) {
            const int kk = ks * 8;
            unsigned af[4][4], bf[4][2];
            #pragma unroll
            for (int fm = 0; fm < 4; fm++) {
                const int rb = wm * 64 + fm * 16;
                af[fm][0] = tf32u(Ab[(rb + g)     * GSTR + kk + t]);
                af[fm][1] = tf32u(Ab[(rb + g + 8) * GSTR + kk + t]);
                af[fm][2] = tf32u(Ab[(rb + g)     * GSTR + kk + t + 4]);
                af[fm][3] = tf32u(Ab[(rb + g + 8) * GSTR + kk + t + 4]);
            }
            #pragma unroll
            for (int fn = 0; fn < 4; fn++) {
                const int nb = wn * 32 + fn * 8;
                bf[fn][0] = tf32u(Bb[(nb + g) * GSTR + kk + t]);
                bf[fn][1] = tf32u(Bb[(nb + g) * GSTR + kk + t + 4]);
            }
            #pragma unroll
            for (int fm = 0; fm < 4; fm++)
                #pragma unroll
                for (int fn = 0; fn < 4; fn++)
                    mma_tf32(acc[fm][fn], af[fm][0], af[fm][1], af[fm][2], af[fm][3],
                             bf[fn][0], bf[fn][1]);
        }
        __syncthreads();
    }

    #pragma unroll
    for (int fm = 0; fm < 4; fm++) {
        const int row = blockIdx.y * 128 + wm * 64 + fm * 16 + g;
        #pragma unroll
        for (int fn = 0; fn < 4; fn++) {
            const int col = blockIdx.x * 128 + wn * 32 + fn * 8 + 2 * t;
            const float bx = bias[col];
            const float by = bias[col + 1];
            float2 r0 = make_float2(acc[fm][fn][0] + bx, acc[fm][fn][1] + by);
            float2 r1 = make_float2(acc[fm][fn][2] + bx, acc[fm][fn][3] + by);
            *(float2*)&out[(size_t)row * D_ + col]       = r0;
            *(float2*)&out[(size_t)(row + 8) * D_ + col] = r1;
        }
    }
}

// ---------------------------------------------------------------------------
// Rotary applied in-place to g_q and g_k.
// ---------------------------------------------------------------------------
__global__ __launch_bounds__(256) void rotary_kernel(const float* __restrict__ cosb,
                                                     const float* __restrict__ sinb)
{
    int idx = blockIdx.x * blockDim.x + threadIdx.x;
    int j  = idx & 31;
    int h  = (idx >> 5) & 15;
    int ms = idx >> 9;
    int s  = ms & (S_ - 1);

    float c1 = cosb[s*HD_ + j],      s1 = sinb[s*HD_ + j];
    float c2 = cosb[s*HD_ + j + 32], s2 = sinb[s*HD_ + j + 32];

    size_t base = (size_t)ms * D_ + h * HD_;
    float q1 = g_q[base + j], q2 = g_q[base + j + 32];
    g_q[base + j]      = q1 * c1 - q2 * s1;
    g_q[base + j + 32] = q2 * c2 + q1 * s2;
    float k1 = g_k[base + j], k2 = g_k[base + j + 32];
    g_k[base + j]      = k1 * c1 - k2 * s1;
    g_k[base + j + 32] = k2 * c2 + k1 * s2;
}

// ---------------------------------------------------------------------------
// Tensor-core flash attention (tf32), causal, cp.async double-buffered K/V.
// Block = (b,h) x 128-query tile, 256 threads (8 warps x 16 rows).
// Q frags in registers; QPs buffer reused for P (warp-private rows).
// K stride 76 (bank = 12g+t, conflict-free). V stride 72 (bank = 8t+g,
// conflict-free). tf32 cvt at fragment load (K/V) / at store (Q,P).
// ---------------------------------------------------------------------------
#define QSTR 68
#define KSTR 76
#define VSTR 72
#define QP_FLOATS (128*QSTR)
#define KT_FLOATS (64*KSTR)
#define VT_FLOATS (64*VSTR)
#define ATT_SMEM_BYTES ((QP_FLOATS + 2*KT_FLOATS + 2*VT_FLOATS) * 4)

__global__ __launch_bounds__(256) void attn_tc()
{
    extern __shared__ float sm[];
    float* QPs = sm;                              // [128][QSTR]
    float* Ks  = sm + QP_FLOATS;                  // [2][64][KSTR]
    float* Vs  = Ks + 2 * KT_FLOATS;              // [2][64][VSTR]

    const int qt = (int)gridDim.x - 1 - (int)blockIdx.x;  // heavy tiles first
    const int bh = blockIdx.y;
    const int b  = bh >> 4;
    const int h  = bh & 15;
    const int q0 = qt * 128;

    const int tid  = threadIdx.x;
    const int warp = tid >> 5;
    const int lane = tid & 31;
    const int g    = lane >> 2;
    const int t    = lane & 3;
    const int rb   = warp * 16;

    const unsigned sK = (unsigned)__cvta_generic_to_shared(Ks);
    const unsigned sV = (unsigned)__cvta_generic_to_shared(Vs);

    // issue K/V tile kt into buffer `buf`
    auto issueKV = [&](int kt, int buf) {
        const int k0 = kt * 64;
        #pragma unroll
        for (int it = 0; it < 4; it++) {
            int idx = tid + it * 256;      // 0..1023
            int j   = idx >> 4;            // 0..63
            int d4  = (idx & 15) * 4;      // 0..60
            size_t go = (size_t)(b*S_ + k0 + j) * D_ + h*HD_ + d4;
            cpa16(sK + (unsigned)(buf * KT_FLOATS + j * KSTR + d4) * 4, g_k + go);
            cpa16(sV + (unsigned)(buf * VT_FLOATS + j * VSTR + d4) * 4, g_v + go);
        }
        CP_COMMIT();
    };

    issueKV(0, 0);

    // ---- load Q tile (scaled by 1/8, tf32-rounded), layout [i][d] ----
    #pragma unroll
    for (int it = 0; it < 8; it++) {
        int l  = tid + it * 256;
        int i  = l >> 4;
        int d4 = (l & 15) * 4;
        float4 qv = *(const float4*)&g_q[(size_t)(b*S_ + q0 + i) * D_ + h*HD_ + d4];
        float4 cv = make_float4(tf32f(qv.x * 0.125f), tf32f(qv.y * 0.125f),
                                tf32f(qv.z * 0.125f), tf32f(qv.w * 0.125f));
        *(float4*)&QPs[i * QSTR + d4] = cv;
    }
    __syncthreads();

    // ---- Q fragments -> registers (own 16 rows only) ----
    unsigned qa[8][4];
    #pragma unroll
    for (int ks = 0; ks < 8; ks++) {
        int kk = ks * 8;
        qa[ks][0] = __float_as_uint(QPs[(rb + g)     * QSTR + kk + t]);
        qa[ks][1] = __float_as_uint(QPs[(rb + g + 8) * QSTR + kk + t]);
        qa[ks][2] = __float_as_uint(QPs[(rb + g)     * QSTR + kk + t + 4]);
        qa[ks][3] = __float_as_uint(QPs[(rb + g + 8) * QSTR + kk + t + 4]);
    }
    // From here QPs rows [rb, rb+16) are warp-private (P buffer).

    float m_lo = -1e30f, m_hi = -1e30f, l_lo = 0.f, l_hi = 0.f;
    float oacc[8][4];
    #pragma unroll
    for (int nf = 0; nf < 8; nf++)
        #pragma unroll
        for (int r = 0; r < 4; r++) oacc[nf][r] = 0.f;

    const int nkt = 2 * qt + 2;
    for (int kt = 0; kt < nkt; kt++) {
        const int buf = kt & 1;
        const int k0  = kt * 64;
        if (kt + 1 < nkt) { issueKV(kt + 1, (kt + 1) & 1); CP_WAIT1(); }
        else              { CP_WAIT0(); }
        __syncthreads();

        const float* Kb = Ks + buf * KT_FLOATS;
        const float* Vb = Vs + buf * VT_FLOATS;

        // ---- S = (Q/8) K^T : 16x64 per warp ----
        float sacc[8][4];
        #pragma unroll
        for (int nf = 0; nf < 8; nf++)
            #pragma unroll
            for (int r = 0; r < 4; r++) sacc[nf][r] = 0.f;

        #pragma unroll
        for (int ks = 0; ks < 8; ks++) {
            int kk = ks * 8;
            #pragma unroll
            for (int nf = 0; nf < 8; nf++) {
                unsigned b0 = tf32u(Kb[(nf*8 + g) * KSTR + kk + t]);
                unsigned b1 = tf32u(Kb[(nf*8 + g) * KSTR + kk + t + 4]);
                mma_tf32(sacc[nf], qa[ks][0], qa[ks][1], qa[ks][2], qa[ks][3], b0, b1);
            }
        }

        // ---- causal mask (only last two k-tiles can cross the diagonal) ----
        if (kt >= nkt - 2) {
            const int rlo = q0 + rb + g;
            #pragma unroll
            for (int nf = 0; nf < 8; nf++) {
                int c0 = k0 + nf*8 + 2*t;
                int c1 = c0 + 1;
                if (c0 > rlo)     sacc[nf][0] = -1e30f;
                if (c1 > rlo)     sacc[nf][1] = -1e30f;
                if (c0 > rlo + 8) sacc[nf][2] = -1e30f;
                if (c1 > rlo + 8) sacc[nf][3] = -1e30f;
            }
        }

        // ---- online softmax (rows g and g+8) ----
        float mx_lo = -1e30f, mx_hi = -1e30f;
        #pragma unroll
        for (int nf = 0; nf < 8; nf++) {
            mx_lo = fmaxf(mx_lo, fmaxf(sacc[nf][0], sacc[nf][1]));
            mx_hi = fmaxf(mx_hi, fmaxf(sacc[nf][2], sacc[nf][3]));
        }
        mx_lo = fmaxf(mx_lo, __shfl_xor_sync(0xffffffffu, mx_lo, 1));
        mx_lo = fmaxf(mx_lo, __shfl_xor_sync(0xffffffffu, mx_lo, 2));
        mx_hi = fmaxf(mx_hi, __shfl_xor_sync(0xffffffffu, mx_hi, 1));
        mx_hi = fmaxf(mx_hi, __shfl_xor_sync(0xffffffffu, mx_hi, 2));

        float mn_lo = fmaxf(m_lo, mx_lo);
        float mn_hi = fmaxf(m_hi, mx_hi);
        float r_lo  = __expf(m_lo - mn_lo);
        float r_hi  = __expf(m_hi - mn_hi);

        float sum_lo = 0.f, sum_hi = 0.f;
        #pragma unroll
        for (int nf = 0; nf < 8; nf++) {
            sacc[nf][0] = __expf(sacc[nf][0] - mn_lo);
            sacc[nf][1] = __expf(sacc[nf][1] - mn_lo);
            sacc[nf][2] = __expf(sacc[nf][2] - mn_hi);
            sacc[nf][3] = __expf(sacc[nf][3] - mn_hi);
            sum_lo += sacc[nf][0] + sacc[nf][1];
            sum_hi += sacc[nf][2] + sacc[nf][3];
        }
        sum_lo += __shfl_xor_sync(0xffffffffu, sum_lo, 1);
        sum_lo += __shfl_xor_sync(0xffffffffu, sum_lo, 2);
        sum_hi += __shfl_xor_sync(0xffffffffu, sum_hi, 1);
        sum_hi += __shfl_xor_sync(0xffffffffu, sum_hi, 2);

        l_lo = l_lo * r_lo + sum_lo;  m_lo = mn_lo;
        l_hi = l_hi * r_hi + sum_hi;  m_hi = mn_hi;

        #pragma unroll
        for (int nf = 0; nf < 8; nf++) {
            oacc[nf][0] *= r_lo;  oacc[nf][1] *= r_lo;
            oacc[nf][2] *= r_hi;  oacc[nf][3] *= r_hi;
        }

        // ---- store P (tf32) into warp-private rows of QPs ----
        #pragma unroll
        for (int nf = 0; nf < 8; nf++) {
            *(float2*)&QPs[(rb + g)     * QSTR + nf*8 + 2*t] =
                make_float2(tf32f(sacc[nf][0]), tf32f(sacc[nf][1]));
            *(float2*)&QPs[(rb + g + 8) * QSTR + nf*8 + 2*t] =
                make_float2(tf32f(sacc[nf][2]), tf32f(sacc[nf][3]));
        }
        __syncwarp();

        // ---- O += P V : B-frag from Vb[k=j][n=d], bank = 8t+g (clean) ----
        #pragma unroll
        for (int ks = 0; ks < 8; ks++) {
            int kk = ks * 8;
            unsigned p0 = __float_as_uint(QPs[(rb + g)     * QSTR + kk + t]);
            unsigned p1 = __float_as_uint(QPs[(rb + g + 8) * QSTR + kk + t]);
            unsigned p2 = __float_as_uint(QPs[(rb + g)     * QSTR + kk + t + 4]);
            unsigned p3 = __float_as_uint(QPs[(rb + g + 8) * QSTR + kk + t + 4]);
            #pragma unroll
            for (int nf = 0; nf < 8; nf++) {
                unsigned b0 = tf32u(Vb[(kk + t)     * VSTR + nf*8 + g]);
                unsigned b1 = tf32u(Vb[(kk + t + 4) * VSTR + nf*8 + g]);
                mma_tf32(oacc[nf], p0, p1, p2, p3, b0, b1);
            }
        }
        __syncthreads();   // all warps done with buf before it is refilled
    }

    // ---- epilogue ----
    const float inv_lo = 1.f / l_lo;
    const float inv_hi = 1.f / l_hi;
    #pragma unroll
    for (int nf = 0; nf < 8; nf++) {
        size_t off = (size_t)(b*S_ + q0 + rb + g) * D_ + h*HD_ + nf*8 + 2*t;
        *(float2*)&g_ctx[off] =
            make_float2(oacc[nf][0] * inv_lo, oacc[nf][1] * inv_lo);
        *(float2*)&g_ctx[off + (size_t)8 * D_] =
            make_float2(oacc[nf][2] * inv_hi, oacc[nf][3] * inv_hi);
    }
}

// ---------------------------------------------------------------------------
extern "C" void kernel_launch(void* const* d_in, const int* in_sizes, int n_in,
                              void* d_out, int out_size)
{
    const float* x    = (const float*)d_in[0];
    const float* cosb = (const float*)d_in[1];
    const float* sinb = (const float*)d_in[2];
    // d_in[3] = attn_mask (causal; implemented analytically)
    const float* Wq = (const float*)d_in[4];
    const float* bq = (const float*)d_in[5];
    const float* Wk = (const float*)d_in[6];
    const float* bk = (const float*)d_in[7];
    const float* Wv = (const float*)d_in[8];
    const float* bv = (const float*)d_in[9];
    const float* Wo = (const float*)d_in[10];
    const float* bo = (const float*)d_in[11];
    float* out = (float*)d_out;

    float *q, *k, *v, *ctx;
    cudaGetSymbolAddress((void**)&q,   g_q);
    cudaGetSymbolAddress((void**)&k,   g_k);
    cudaGetSymbolAddress((void**)&v,   g_v);
    cudaGetSymbolAddress((void**)&ctx, g_ctx);

    cudaFuncSetAttribute(gemm_tf32,
                         cudaFuncAttributeMaxDynamicSharedMemorySize,
                         GEMM_SMEM_BYTES);
    cudaFuncSetAttribute(attn_tc,
                         cudaFuncAttributeMaxDynamicSharedMemorySize,
                         ATT_SMEM_BYTES);

    dim3 gg(D_/128, M_/128);   // (8, 64)
    gemm_tf32<<<gg, 256, GEMM_SMEM_BYTES>>>(x, Wq, bq, q);
    gemm_tf32<<<gg, 256, GEMM_SMEM_BYTES>>>(x, Wk, bk, k);
    gemm_tf32<<<gg, 256, GEMM_SMEM_BYTES>>>(x, Wv, bv, v);

    rotary_kernel<<<(M_*H_*32)/256, 256>>>(cosb, sinb);

    attn_tc<<<dim3(S_/128, B_*H_), 256, ATT_SMEM_BYTES>>>();

    gemm_tf32<<<gg, 256, GEMM_SMEM_BYTES>>>(ctx, Wo, bo, out);
}

// round 10
// speedup vs baseline: 2.9536x; 1.0497x over previous
#include <cuda_runtime.h>
#include <math.h>

#define B_  4
#define S_  2048
#define D_  1024
#define H_  16
#define HD_ 64
#define M_  (B_*S_)

__device__ float g_q[M_*D_];
__device__ float g_k[M_*D_];
__device__ float g_v[M_*D_];
__device__ float g_ctx[M_*D_];

__device__ __forceinline__ unsigned tf32u(float f) {
    unsigned u;
    asm("cvt.rna.tf32.f32 %0, %1;" : "=r"(u) : "f"(f));
    return u;
}
__device__ __forceinline__ float tf32f(float f) { return __uint_as_float(tf32u(f)); }

__device__ __forceinline__ void mma_tf32(float* c,
                                         unsigned a0, unsigned a1, unsigned a2, unsigned a3,
                                         unsigned b0, unsigned b1)
{
    asm volatile(
        "mma.sync.aligned.m16n8k8.row.col.f32.tf32.tf32.f32 "
        "{%0,%1,%2,%3}, {%4,%5,%6,%7}, {%8,%9}, {%0,%1,%2,%3};"
        : "+f"(c[0]), "+f"(c[1]), "+f"(c[2]), "+f"(c[3])
        : "r"(a0), "r"(a1), "r"(a2), "r"(a3), "r"(b0), "r"(b1));
}

__device__ __forceinline__ void cpa16(unsigned saddr, const void* gptr) {
    asm volatile("cp.async.cg.shared.global [%0], [%1], 16;" :: "r"(saddr), "l"(gptr));
}
#define CP_COMMIT() asm volatile("cp.async.commit_group;")
#define CP_WAIT0()  asm volatile("cp.async.wait_group 0;")

// ---------------------------------------------------------------------------
// TF32 GEMM: out[m,n] = sum_k A[m,k]*W[n,k] + bias[n].  M=8192, N=K=1024.
// 256x128 block tile (halves L2 traffic vs 128x128), BK=32, 512 threads
// (16 warps, 4x4; warp tile 64x32). cp.async double-buffered, ONE sync/iter.
// Smem stride 36 (=4 mod 32): fragment LDS bank = 4g+t(+kk), conflict-free.
// ---------------------------------------------------------------------------
#define GK   32
#define GSTR 36
#define AS_FLOATS (256*GSTR)
#define BS_FLOATS (128*GSTR)
#define GEMM_SMEM_BYTES (2*(AS_FLOATS + BS_FLOATS)*4)   // 110,592 B

__global__ __launch_bounds__(512) void gemm_tf32(const float* __restrict__ A,
                                                 const float* __restrict__ W,
                                                 const float* __restrict__ bias,
                                                 float* __restrict__ out)
{
    extern __shared__ float smg[];
    float* As = smg;                       // [2][256*GSTR]
    float* Bs = smg + 2 * AS_FLOATS;       // [2][128*GSTR]

    const int tid  = threadIdx.x;
    const int warp = tid >> 5;
    const int lane = tid & 31;
    const int g    = lane >> 2;
    const int t    = lane & 3;
    const int wm   = warp & 3;     // 4 x 64 rows
    const int wn   = warp >> 2;    // 4 x 32 cols

    const float* Abase = A + (size_t)(blockIdx.y * 256) * D_;
    const float* Wbase = W + (size_t)(blockIdx.x * 128) * D_;

    const unsigned sA = (unsigned)__cvta_generic_to_shared(As);
    const unsigned sB = (unsigned)__cvta_generic_to_shared(Bs);

    float acc[4][4][4];
    #pragma unroll
    for (int i = 0; i < 4; i++)
        #pragma unroll
        for (int j = 0; j < 4; j++)
            #pragma unroll
            for (int r = 0; r < 4; r++) acc[i][j][r] = 0.f;

    auto issue = [&](int kt, int buf) {
        const int k0 = kt * GK;
        #pragma unroll
        for (int it = 0; it < 4; it++) {               // A: 256x32 = 2048 float4
            int idx = tid + it * 512;
            int row = idx >> 3;
            int c4  = (idx & 7) * 4;
            cpa16(sA + (unsigned)(buf * AS_FLOATS + row * GSTR + c4) * 4,
                  Abase + (size_t)row * D_ + k0 + c4);
        }
        #pragma unroll
        for (int it = 0; it < 2; it++) {               // B: 128x32 = 1024 float4
            int idx = tid + it * 512;
            int row = idx >> 3;
            int c4  = (idx & 7) * 4;
            cpa16(sB + (unsigned)(buf * BS_FLOATS + row * GSTR + c4) * 4,
                  Wbase + (size_t)row * D_ + k0 + c4);
        }
        CP_COMMIT();
    };

    issue(0, 0);
    const int NKT = D_ / GK;   // 32
    for (int kt = 0; kt < NKT; kt++) {
        const int buf = kt & 1;
        CP_WAIT0();
        __syncthreads();
        if (kt + 1 < NKT) issue(kt + 1, (kt + 1) & 1);

        const float* Ab = As + buf * AS_FLOATS;
        const float* Bb = Bs + buf * BS_FLOATS;
        #pragma unroll
        for (int ks = 0; ks < 4; ks++) {
            const int kk = ks * 8;
            unsigned af[4][4], bf[4][2];
            #pragma unroll
            for (int fm = 0; fm < 4; fm++) {
                const int rb = wm * 64 + fm * 16;
                af[fm][0] = tf32u(Ab[(rb + g)     * GSTR + kk + t]);
                af[fm][1] = tf32u(Ab[(rb + g + 8) * GSTR + kk + t]);
                af[fm][2] = tf32u(Ab[(rb + g)     * GSTR + kk + t + 4]);
                af[fm][3] = tf32u(Ab[(rb + g + 8) * GSTR + kk + t + 4]);
            }
            #pragma unroll
            for (int fn = 0; fn < 4; fn++) {
                const int nb = wn * 32 + fn * 8;
                bf[fn][0] = tf32u(Bb[(nb + g) * GSTR + kk + t]);
                bf[fn][1] = tf32u(Bb[(nb + g) * GSTR + kk + t + 4]);
            }
            #pragma unroll
            for (int fm = 0; fm < 4; fm++)
                #pragma unroll
                for (int fn = 0; fn < 4; fn++)
                    mma_tf32(acc[fm][fn], af[fm][0], af[fm][1], af[fm][2], af[fm][3],
                             bf[fn][0], bf[fn][1]);
        }
    }

    #pragma unroll
    for (int fm = 0; fm < 4; fm++) {
        const int row = blockIdx.y * 256 + wm * 64 + fm * 16 + g;
        #pragma unroll
        for (int fn = 0; fn < 4; fn++) {
            const int col = blockIdx.x * 128 + wn * 32 + fn * 8 + 2 * t;
            const float bx = bias[col];
            const float by = bias[col + 1];
            float2 r0 = make_float2(acc[fm][fn][0] + bx, acc[fm][fn][1] + by);
            float2 r1 = make_float2(acc[fm][fn][2] + bx, acc[fm][fn][3] + by);
            *(float2*)&out[(size_t)row * D_ + col]       = r0;
            *(float2*)&out[(size_t)(row + 8) * D_ + col] = r1;
        }
    }
}

// ---------------------------------------------------------------------------
// Rotary applied in-place to g_q and g_k.
// ---------------------------------------------------------------------------
__global__ __launch_bounds__(256) void rotary_kernel(const float* __restrict__ cosb,
                                                     const float* __restrict__ sinb)
{
    int idx = blockIdx.x * blockDim.x + threadIdx.x;
    int j  = idx & 31;
    int h  = (idx >> 5) & 15;
    int ms = idx >> 9;
    int s  = ms & (S_ - 1);

    float c1 = cosb[s*HD_ + j],      s1 = sinb[s*HD_ + j];
    float c2 = cosb[s*HD_ + j + 32], s2 = sinb[s*HD_ + j + 32];

    size_t base = (size_t)ms * D_ + h * HD_;
    float q1 = g_q[base + j], q2 = g_q[base + j + 32];
    g_q[base + j]      = q1 * c1 - q2 * s1;
    g_q[base + j + 32] = q2 * c2 + q1 * s2;
    float k1 = g_k[base + j], k2 = g_k[base + j + 32];
    g_k[base + j]      = k1 * c1 - k2 * s1;
    g_k[base + j + 32] = k2 * c2 + k1 * s2;
}

// ---------------------------------------------------------------------------
// Tensor-core flash attention (tf32), causal, Bc=128 K/V tiles,
// cp.async double-buffered, ONE sync per iter.
// Block = (b,h) x 128-query tile, 256 threads (8 warps x 16 rows).
// QP buffer [128][132] holds Q (first 64 cols) then P (warp-private rows).
// Banks: P-load 4g+t ok; K 12g+t ok; V 8t+g ok.
// ---------------------------------------------------------------------------
#define PSTR 132
#define KSTR 76
#define VSTR 72
#define QP_FLOATS (128*PSTR)
#define KT_FLOATS (128*KSTR)
#define VT_FLOATS (128*VSTR)
#define ATT_SMEM_BYTES ((QP_FLOATS + 2*KT_FLOATS + 2*VT_FLOATS) * 4)  // 219,136 B

__global__ __launch_bounds__(256) void attn_tc()
{
    extern __shared__ float sm[];
    float* QPs = sm;                              // [128][PSTR]
    float* Ks  = sm + QP_FLOATS;                  // [2][128][KSTR]
    float* Vs  = Ks + 2 * KT_FLOATS;              // [2][128][VSTR]

    const int qt = (int)gridDim.x - 1 - (int)blockIdx.x;  // heavy tiles first
    const int bh = blockIdx.y;
    const int b  = bh >> 4;
    const int h  = bh & 15;
    const int q0 = qt * 128;

    const int tid  = threadIdx.x;
    const int warp = tid >> 5;
    const int lane = tid & 31;
    const int g    = lane >> 2;
    const int t    = lane & 3;
    const int rb   = warp * 16;

    const unsigned sK = (unsigned)__cvta_generic_to_shared(Ks);
    const unsigned sV = (unsigned)__cvta_generic_to_shared(Vs);

    auto issueKV = [&](int kt, int buf) {
        const int k0 = kt * 128;
        #pragma unroll
        for (int it = 0; it < 8; it++) {
            int idx = tid + it * 256;      // 0..2047
            int j   = idx >> 4;            // 0..127
            int d4  = (idx & 15) * 4;      // 0..60
            size_t go = (size_t)(b*S_ + k0 + j) * D_ + h*HD_ + d4;
            cpa16(sK + (unsigned)(buf * KT_FLOATS + j * KSTR + d4) * 4, g_k + go);
            cpa16(sV + (unsigned)(buf * VT_FLOATS + j * VSTR + d4) * 4, g_v + go);
        }
        CP_COMMIT();
    };

    issueKV(0, 0);

    // ---- load Q tile (scaled by 1/8, tf32-rounded) into QPs[i][0..63] ----
    #pragma unroll
    for (int it = 0; it < 8; it++) {
        int l  = tid + it * 256;
        int i  = l >> 4;
        int d4 = (l & 15) * 4;
        float4 qv = *(const float4*)&g_q[(size_t)(b*S_ + q0 + i) * D_ + h*HD_ + d4];
        float4 cv = make_float4(tf32f(qv.x * 0.125f), tf32f(qv.y * 0.125f),
                                tf32f(qv.z * 0.125f), tf32f(qv.w * 0.125f));
        *(float4*)&QPs[i * PSTR + d4] = cv;
    }
    __syncthreads();

    // ---- Q fragments -> registers (own 16 rows only) ----
    unsigned qa[8][4];
    #pragma unroll
    for (int ks = 0; ks < 8; ks++) {
        int kk = ks * 8;
        qa[ks][0] = __float_as_uint(QPs[(rb + g)     * PSTR + kk + t]);
        qa[ks][1] = __float_as_uint(QPs[(rb + g + 8) * PSTR + kk + t]);
        qa[ks][2] = __float_as_uint(QPs[(rb + g)     * PSTR + kk + t + 4]);
        qa[ks][3] = __float_as_uint(QPs[(rb + g + 8) * PSTR + kk + t + 4]);
    }
    // From here QPs rows [rb, rb+16) are warp-private (P buffer).

    float m_lo = -1e30f, m_hi = -1e30f, l_lo = 0.f, l_hi = 0.f;
    float oacc[8][4];
    #pragma unroll
    for (int nf = 0; nf < 8; nf++)
        #pragma unroll
        for (int r = 0; r < 4; r++) oacc[nf][r] = 0.f;

    const int nkt = qt + 1;
    for (int kt = 0; kt < nkt; kt++) {
        const int buf = kt & 1;
        const int k0  = kt * 128;
        CP_WAIT0();
        __syncthreads();
        if (kt + 1 < nkt) issueKV(kt + 1, (kt + 1) & 1);

        const float* Kb = Ks + buf * KT_FLOATS;
        const float* Vb = Vs + buf * VT_FLOATS;

        // ---- S = (Q/8) K^T : 16x128 per warp ----
        float sacc[16][4];
        #pragma unroll
        for (int nf = 0; nf < 16; nf++)
            #pragma unroll
            for (int r = 0; r < 4; r++) sacc[nf][r] = 0.f;

        #pragma unroll
        for (int ks = 0; ks < 8; ks++) {
            int kk = ks * 8;
            #pragma unroll
            for (int nf = 0; nf < 16; nf++) {
                unsigned b0 = tf32u(Kb[(nf*8 + g) * KSTR + kk + t]);
                unsigned b1 = tf32u(Kb[(nf*8 + g) * KSTR + kk + t + 4]);
                mma_tf32(sacc[nf], qa[ks][0], qa[ks][1], qa[ks][2], qa[ks][3], b0, b1);
            }
        }

        // ---- causal mask (diagonal tile only) ----
        if (kt == nkt - 1) {
            const int rlo = q0 + rb + g;
            #pragma unroll
            for (int nf = 0; nf < 16; nf++) {
                int c0 = k0 + nf*8 + 2*t;
                int c1 = c0 + 1;
                if (c0 > rlo)     sacc[nf][0] = -1e30f;
                if (c1 > rlo)     sacc[nf][1] = -1e30f;
                if (c0 > rlo + 8) sacc[nf][2] = -1e30f;
                if (c1 > rlo + 8) sacc[nf][3] = -1e30f;
            }
        }

        // ---- online softmax (rows g and g+8) ----
        float mx_lo = -1e30f, mx_hi = -1e30f;
        #pragma unroll
        for (int nf = 0; nf < 16; nf++) {
            mx_lo = fmaxf(mx_lo, fmaxf(sacc[nf][0], sacc[nf][1]));
            mx_hi = fmaxf(mx_hi, fmaxf(sacc[nf][2], sacc[nf][3]));
        }
        mx_lo = fmaxf(mx_lo, __shfl_xor_sync(0xffffffffu, mx_lo, 1));
        mx_lo = fmaxf(mx_lo, __shfl_xor_sync(0xffffffffu, mx_lo, 2));
        mx_hi = fmaxf(mx_hi, __shfl_xor_sync(0xffffffffu, mx_hi, 1));
        mx_hi = fmaxf(mx_hi, __shfl_xor_sync(0xffffffffu, mx_hi, 2));

        float mn_lo = fmaxf(m_lo, mx_lo);
        float mn_hi = fmaxf(m_hi, mx_hi);
        float r_lo  = __expf(m_lo - mn_lo);
        float r_hi  = __expf(m_hi - mn_hi);

        float sum_lo = 0.f, sum_hi = 0.f;
        #pragma unroll
        for (int nf = 0; nf < 16; nf++) {
            sacc[nf][0] = __expf(sacc[nf][0] - mn_lo);
            sacc[nf][1] = __expf(sacc[nf][1] - mn_lo);
            sacc[nf][2] = __expf(sacc[nf][2] - mn_hi);
            sacc[nf][3] = __expf(sacc[nf][3] - mn_hi);
            sum_lo += sacc[nf][0] + sacc[nf][1];
            sum_hi += sacc[nf][2] + sacc[nf][3];
        }
        sum_lo += __shfl_xor_sync(0xffffffffu, sum_lo, 1);
        sum_lo += __shfl_xor_sync(0xffffffffu, sum_lo, 2);
        sum_hi += __shfl_xor_sync(0xffffffffu, sum_hi, 1);
        sum_hi += __shfl_xor_sync(0xffffffffu, sum_hi, 2);

        l_lo = l_lo * r_lo + sum_lo;  m_lo = mn_lo;
        l_hi = l_hi * r_hi + sum_hi;  m_hi = mn_hi;

        #pragma unroll
        for (int nf = 0; nf < 8; nf++) {
            oacc[nf][0] *= r_lo;  oacc[nf][1] *= r_lo;
            oacc[nf][2] *= r_hi;  oacc[nf][3] *= r_hi;
        }

        // ---- store P (tf32) into warp-private rows of QPs ----
        #pragma unroll
        for (int nf = 0; nf < 16; nf++) {
            *(float2*)&QPs[(rb + g)     * PSTR + nf*8 + 2*t] =
                make_float2(tf32f(sacc[nf][0]), tf32f(sacc[nf][1]));
            *(float2*)&QPs[(rb + g + 8) * PSTR + nf*8 + 2*t] =
                make_float2(tf32f(sacc[nf][2]), tf32f(sacc[nf][3]));
        }
        __syncwarp();

        // ---- O += P V : k-dim 128 (16 steps), d-out 64 (8 frags) ----
        #pragma unroll
        for (int ks = 0; ks < 16; ks++) {
            int kk = ks * 8;
            unsigned p0 = __float_as_uint(QPs[(rb + g)     * PSTR + kk + t]);
            unsigned p1 = __float_as_uint(QPs[(rb + g + 8) * PSTR + kk + t]);
            unsigned p2 = __float_as_uint(QPs[(rb + g)     * PSTR + kk + t + 4]);
            unsigned p3 = __float_as_uint(QPs[(rb + g + 8) * PSTR + kk + t + 4]);
            #pragma unroll
            for (int nf = 0; nf < 8; nf++) {
                unsigned b0 = tf32u(Vb[(kk + t)     * VSTR + nf*8 + g]);
                unsigned b1 = tf32u(Vb[(kk + t + 4) * VSTR + nf*8 + g]);
                mma_tf32(oacc[nf], p0, p1, p2, p3, b0, b1);
            }
        }
    }

    // ---- epilogue ----
    const float inv_lo = 1.f / l_lo;
    const float inv_hi = 1.f / l_hi;
    #pragma unroll
    for (int nf = 0; nf < 8; nf++) {
        size_t off = (size_t)(b*S_ + q0 + rb + g) * D_ + h*HD_ + nf*8 + 2*t;
        *(float2*)&g_ctx[off] =
            make_float2(oacc[nf][0] * inv_lo, oacc[nf][1] * inv_lo);
        *(float2*)&g_ctx[off + (size_t)8 * D_] =
            make_float2(oacc[nf][2] * inv_hi, oacc[nf][3] * inv_hi);
    }
}

// ---------------------------------------------------------------------------
extern "C" void kernel_launch(void* const* d_in, const int* in_sizes, int n_in,
                              void* d_out, int out_size)
{
    const float* x    = (const float*)d_in[0];
    const float* cosb = (const float*)d_in[1];
    const float* sinb = (const float*)d_in[2];
    // d_in[3] = attn_mask (causal; implemented analytically)
    const float* Wq = (const float*)d_in[4];
    const float* bq = (const float*)d_in[5];
    const float* Wk = (const float*)d_in[6];
    const float* bk = (const float*)d_in[7];
    const float* Wv = (const float*)d_in[8];
    const float* bv = (const float*)d_in[9];
    const float* Wo = (const float*)d_in[10];
    const float* bo = (const float*)d_in[11];
    float* out = (float*)d_out;

    float *q, *k, *v, *ctx;
    cudaGetSymbolAddress((void**)&q,   g_q);
    cudaGetSymbolAddress((void**)&k,   g_k);
    cudaGetSymbolAddress((void**)&v,   g_v);
    cudaGetSymbolAddress((void**)&ctx, g_ctx);

    cudaFuncSetAttribute(gemm_tf32,
                         cudaFuncAttributeMaxDynamicSharedMemorySize,
                         GEMM_SMEM_BYTES);
    cudaFuncSetAttribute(attn_tc,
                         cudaFuncAttributeMaxDynamicSharedMemorySize,
                         ATT_SMEM_BYTES);

    dim3 gg(D_/128, M_/256);   // (8, 32)
    gemm_tf32<<<gg, 512, GEMM_SMEM_BYTES>>>(x, Wq, bq, q);
    gemm_tf32<<<gg, 512, GEMM_SMEM_BYTES>>>(x, Wk, bk, k);
    gemm_tf32<<<gg, 512, GEMM_SMEM_BYTES>>>(x, Wv, bv, v);

    rotary_kernel<<<(M_*H_*32)/256, 256>>>(cosb, sinb);

    attn_tc<<<dim3(S_/128, B_*H_), 256, ATT_SMEM_BYTES>>>();

    gemm_tf32<<<gg, 512, GEMM_SMEM_BYTES>>>(ctx, Wo, bo, out);
}

// round 12
// speedup vs baseline: 5.2905x; 1.7912x over previous
#include <cuda_runtime.h>
#include <cuda_fp16.h>
#include <math.h>

#define B_  4
#define S_  2048
#define D_  1024
#define H_  16
#define HD_ 64
#define M_  (B_*S_)

// Scratch (allocation-free rule: __device__ globals)
__device__ float  g_q[M_*D_];          // fp32 projections (pre-rotary)
__device__ float  g_k[M_*D_];
__device__ float  g_v[M_*D_];
__device__ __half g_xh[M_*D_];         // half inputs for GEMMs
__device__ __half g_wqh[D_*D_];
__device__ __half g_wkh[D_*D_];
__device__ __half g_wvh[D_*D_];
__device__ __half g_woh[D_*D_];
__device__ __half g_qh[M_*D_];         // rotary'd, x0.125
__device__ __half g_kh[M_*D_];
__device__ __half g_vt[M_*D_];         // V transposed: [B*H][64][2048]
__device__ __half g_cth[M_*D_];        // attention output (half)

extern __shared__ float dynsm[];

__device__ __forceinline__ void mma_f16(float* c,
                                        unsigned a0, unsigned a1, unsigned a2, unsigned a3,
                                        unsigned b0, unsigned b1)
{
    asm volatile(
        "mma.sync.aligned.m16n8k16.row.col.f32.f16.f16.f32 "
        "{%0,%1,%2,%3}, {%4,%5,%6,%7}, {%8,%9}, {%0,%1,%2,%3};"
        : "+f"(c[0]), "+f"(c[1]), "+f"(c[2]), "+f"(c[3])
        : "r"(a0), "r"(a1), "r"(a2), "r"(a3), "r"(b0), "r"(b1));
}

__device__ __forceinline__ void cpa16(unsigned saddr, const void* gptr) {
    asm volatile("cp.async.cg.shared.global [%0], [%1], 16;" :: "r"(saddr), "l"(gptr));
}
#define CP_COMMIT() asm volatile("cp.async.commit_group;")
#define CP_WAIT0()  asm volatile("cp.async.wait_group 0;")

__device__ __forceinline__ unsigned ldh2(const __half* p) {
    return *(const unsigned*)p;
}

// ---------------------------------------------------------------------------
// fp32 -> half elementwise
// ---------------------------------------------------------------------------
__global__ __launch_bounds__(256) void f2h_kernel(const float* __restrict__ in,
                                                  __half* __restrict__ out, int n4)
{
    int i = blockIdx.x * blockDim.x + threadIdx.x;
    if (i < n4) {
        float4 v = ((const float4*)in)[i];
        ((__half2*)out)[2*i]     = __floats2half2_rn(v.x, v.y);
        ((__half2*)out)[2*i + 1] = __floats2half2_rn(v.z, v.w);
    }
}

// ---------------------------------------------------------------------------
// FP16 tensor-core GEMM: out[m,n] = sum_k A[m,k]*W[n,k] + bias[n] (fp32 out)
// 256x128 block tile, BK=32, 512 threads (16 warps, warp tile 64x32),
// m16n8k16, cp.async double-buffered, one sync/iter.
// Row stride 40 halves (80B): frag LDS bank = 20g+t (mod 32) conflict-free.
// ---------------------------------------------------------------------------
#define ASH 40
#define GA_HALVES (256*ASH)
#define GB_HALVES (128*ASH)
#define GEMM_SMEM_BYTES (2*(GA_HALVES + GB_HALVES)*2)   // 61,440 B

__global__ __launch_bounds__(512) void gemm_h(const __half* __restrict__ A,
                                              const __half* __restrict__ W,
                                              const float* __restrict__ bias,
                                              float* __restrict__ out)
{
    __half* As = (__half*)dynsm;                 // [2][256*ASH]
    __half* Bs = As + 2 * GA_HALVES;             // [2][128*ASH]

    const int tid  = threadIdx.x;
    const int warp = tid >> 5;
    const int lane = tid & 31;
    const int g    = lane >> 2;
    const int t    = lane & 3;
    const int wm   = warp & 3;     // 4 x 64 rows
    const int wn   = warp >> 2;    // 4 x 32 cols

    const __half* Abase = A + (size_t)(blockIdx.y * 256) * D_;
    const __half* Wbase = W + (size_t)(blockIdx.x * 128) * D_;

    const unsigned sA = (unsigned)__cvta_generic_to_shared(As);
    const unsigned sB = (unsigned)__cvta_generic_to_shared(Bs);

    float acc[4][4][4];
    #pragma unroll
    for (int i = 0; i < 4; i++)
        #pragma unroll
        for (int j = 0; j < 4; j++)
            #pragma unroll
            for (int r = 0; r < 4; r++) acc[i][j][r] = 0.f;

    auto issue = [&](int kt, int buf) {
        const int k0 = kt * 32;                  // in halves (K elements)
        #pragma unroll
        for (int it = 0; it < 2; it++) {         // A: 256 rows x 4 chunks = 1024
            int idx = tid + it * 512;
            int row = idx >> 2;
            int ch  = (idx & 3) * 8;             // halves
            cpa16(sA + (unsigned)(buf * GA_HALVES + row * ASH + ch) * 2,
                  Abase + (size_t)row * D_ + k0 + ch);
        }
        {                                        // B: 128 rows x 4 chunks = 512
            int idx = tid;
            int row = idx >> 2;
            int ch  = (idx & 3) * 8;
            cpa16(sB + (unsigned)(buf * GB_HALVES + row * ASH + ch) * 2,
                  Wbase + (size_t)row * D_ + k0 + ch);
        }
        CP_COMMIT();
    };

    issue(0, 0);
    const int NKT = D_ / 32;   // 32
    for (int kt = 0; kt < NKT; kt++) {
        const int buf = kt & 1;
        CP_WAIT0();
        __syncthreads();
        if (kt + 1 < NKT) issue(kt + 1, buf ^ 1);

        const __half* Ab = As + buf * GA_HALVES;
        const __half* Bb = Bs + buf * GB_HALVES;
        #pragma unroll
        for (int ks = 0; ks < 2; ks++) {
            const int kk = ks * 16;
            unsigned af[4][4], bf[4][2];
            #pragma unroll
            for (int fm = 0; fm < 4; fm++) {
                const int rb = wm * 64 + fm * 16;
                af[fm][0] = ldh2(&Ab[(rb + g)     * ASH + kk + 2*t]);
                af[fm][1] = ldh2(&Ab[(rb + g + 8) * ASH + kk + 2*t]);
                af[fm][2] = ldh2(&Ab[(rb + g)     * ASH + kk + 8 + 2*t]);
                af[fm][3] = ldh2(&Ab[(rb + g + 8) * ASH + kk + 8 + 2*t]);
            }
            #pragma unroll
            for (int fn = 0; fn < 4; fn++) {
                const int nb = wn * 32 + fn * 8;
                bf[fn][0] = ldh2(&Bb[(nb + g) * ASH + kk + 2*t]);
                bf[fn][1] = ldh2(&Bb[(nb + g) * ASH + kk + 8 + 2*t]);
            }
            #pragma unroll
            for (int fm = 0; fm < 4; fm++)
                #pragma unroll
                for (int fn = 0; fn < 4; fn++)
                    mma_f16(acc[fm][fn], af[fm][0], af[fm][1], af[fm][2], af[fm][3],
                            bf[fn][0], bf[fn][1]);
        }
    }

    #pragma unroll
    for (int fm = 0; fm < 4; fm++) {
        const int row = blockIdx.y * 256 + wm * 64 + fm * 16 + g;
        #pragma unroll
        for (int fn = 0; fn < 4; fn++) {
            const int col = blockIdx.x * 128 + wn * 32 + fn * 8 + 2 * t;
            const float bx = bias[col];
            const float by = bias[col + 1];
            float2 r0 = make_float2(acc[fm][fn][0] + bx, acc[fm][fn][1] + by);
            float2 r1 = make_float2(acc[fm][fn][2] + bx, acc[fm][fn][3] + by);
            *(float2*)&out[(size_t)row * D_ + col]       = r0;
            *(float2*)&out[(size_t)(row + 8) * D_ + col] = r1;
        }
    }
}

// ---------------------------------------------------------------------------
// Rotary: read fp32 g_q/g_k, write half g_qh (x0.125) and g_kh.
// ---------------------------------------------------------------------------
__global__ __launch_bounds__(256) void rotary_h_kernel(const float* __restrict__ cosb,
                                                       const float* __restrict__ sinb)
{
    int idx = blockIdx.x * blockDim.x + threadIdx.x;   // over M_*H_*32
    int j  = idx & 31;
    int h  = (idx >> 5) & 15;
    int ms = idx >> 9;
    int s  = ms & (S_ - 1);

    float c1 = cosb[s*HD_ + j],      s1 = sinb[s*HD_ + j];
    float c2 = cosb[s*HD_ + j + 32], s2 = sinb[s*HD_ + j + 32];

    size_t base = (size_t)ms * D_ + h * HD_;
    float q1 = g_q[base + j], q2 = g_q[base + j + 32];
    g_qh[base + j]      = __float2half_rn((q1 * c1 - q2 * s1) * 0.125f);
    g_qh[base + j + 32] = __float2half_rn((q2 * c2 + q1 * s2) * 0.125f);
    float k1 = g_k[base + j], k2 = g_k[base + j + 32];
    g_kh[base + j]      = __float2half_rn(k1 * c1 - k2 * s1);
    g_kh[base + j + 32] = __float2half_rn(k2 * c2 + k1 * s2);
}

// ---------------------------------------------------------------------------
// V transpose: fp32 [b,s,h,d] -> half g_vt[bh][d][s]. 64s x 64d tiles.
// ---------------------------------------------------------------------------
__global__ __launch_bounds__(256) void vtrans_kernel()
{
    __shared__ float ts[64][65];
    const int bh = blockIdx.x;
    const int b  = bh >> 4;
    const int h  = bh & 15;
    const int s0 = blockIdx.y * 64;
    const int tid = threadIdx.x;

    #pragma unroll
    for (int it = 0; it < 4; it++) {
        int l  = tid + it * 256;         // 0..1023 float4 slots
        int r  = l >> 4;                 // s-row 0..63
        int c4 = (l & 15) * 4;           // d 0..60
        float4 v = *(const float4*)&g_v[(size_t)(b*S_ + s0 + r) * D_ + h*HD_ + c4];
        ts[r][c4+0] = v.x; ts[r][c4+1] = v.y; ts[r][c4+2] = v.z; ts[r][c4+3] = v.w;
    }
    __syncthreads();

    #pragma unroll
    for (int it = 0; it < 2; it++) {
        int l  = tid + it * 256;         // 0..511
        int d  = l >> 3;                 // 0..63
        int j8 = (l & 7) * 8;            // 0..56
        __half2* dst = (__half2*)&g_vt[(size_t)(bh*HD_ + d) * S_ + s0 + j8];
        #pragma unroll
        for (int m = 0; m < 4; m++)
            dst[m] = __floats2half2_rn(ts[j8 + 2*m][d], ts[j8 + 2*m + 1][d]);
    }
}

// ---------------------------------------------------------------------------
// FP16 tensor-core flash attention, causal, Bc=128, cp.async double-buffered.
// Block = (b,h) x 128-query tile, 256 threads (8 warps x 16 rows).
// P buffer [128][136h] (Q staged there first; rows warp-private for P).
// K [2][128][72h]; Vt [2][64][136h] (V transposed so PV B-frags are half2).
// Banks: P/Q frag 4g+t; K frag 4g+t; Vt frag 4g+t — all conflict-free.
// ---------------------------------------------------------------------------
#define PSH 136
#define KSH 72
#define VSH 136
#define P_HALVES  (128*PSH)
#define KT_HALVES (128*KSH)
#define VT_HALVES (64*VSH)
#define ATT_SMEM_BYTES ((P_HALVES + 2*KT_HALVES + 2*VT_HALVES) * 2)  // 106,496 B

__global__ __launch_bounds__(256) void attn_h()
{
    __half* Ph = (__half*)dynsm;                 // [128][PSH]
    __half* Kh = Ph + P_HALVES;                  // [2][128][KSH]
    __half* Vh = Kh + 2 * KT_HALVES;             // [2][64][VSH]

    const int qt = (int)gridDim.x - 1 - (int)blockIdx.x;  // heavy tiles first
    const int bh = blockIdx.y;
    const int b  = bh >> 4;
    const int h  = bh & 15;
    const int q0 = qt * 128;

    const int tid  = threadIdx.x;
    const int warp = tid >> 5;
    const int lane = tid & 31;
    const int g    = lane >> 2;
    const int t    = lane & 3;
    const int rb   = warp * 16;

    const unsigned sP = (unsigned)__cvta_generic_to_shared(Ph);
    const unsigned sK = (unsigned)__cvta_generic_to_shared(Kh);
    const unsigned sV = (unsigned)__cvta_generic_to_shared(Vh);

    auto issueKV = [&](int kt, int buf) {
        const int k0 = kt * 128;
        #pragma unroll
        for (int it = 0; it < 4; it++) {         // K: 128 rows x 8 chunks
            int idx = tid + it * 256;
            int j   = idx >> 3;
            int ch  = (idx & 7) * 8;
            cpa16(sK + (unsigned)(buf * KT_HALVES + j * KSH + ch) * 2,
                  g_kh + (size_t)(b*S_ + k0 + j) * D_ + h*HD_ + ch);
        }
        #pragma unroll
        for (int it = 0; it < 4; it++) {         // Vt: 64 rows x 16 chunks
            int idx = tid + it * 256;
            int d   = idx >> 4;
            int ch  = (idx & 15) * 8;
            cpa16(sV + (unsigned)(buf * VT_HALVES + d * VSH + ch) * 2,
                  g_vt + (size_t)(bh*HD_ + d) * S_ + k0 + ch);
        }
        CP_COMMIT();
    };

    // stage Q (half, pre-scaled) into P buffer rows, then issue KV0
    #pragma unroll
    for (int it = 0; it < 4; it++) {             // 128 rows x 8 chunks
        int idx = tid + it * 256;
        int i   = idx >> 3;
        int ch  = (idx & 7) * 8;
        cpa16(sP + (unsigned)(i * PSH + ch) * 2,
              g_qh + (size_t)(b*S_ + q0 + i) * D_ + h*HD_ + ch);
    }
    issueKV(0, 0);
    CP_WAIT0();
    __syncthreads();

    // Q fragments -> registers (own 16 rows only)
    unsigned qa[4][4];
    #pragma unroll
    for (int ks = 0; ks < 4; ks++) {
        int kk = ks * 16;
        qa[ks][0] = ldh2(&Ph[(rb + g)     * PSH + kk + 2*t]);
        qa[ks][1] = ldh2(&Ph[(rb + g + 8) * PSH + kk + 2*t]);
        qa[ks][2] = ldh2(&Ph[(rb + g)     * PSH + kk + 8 + 2*t]);
        qa[ks][3] = ldh2(&Ph[(rb + g + 8) * PSH + kk + 8 + 2*t]);
    }
    // From here Ph rows [rb, rb+16) are warp-private (P buffer).

    float m_lo = -1e30f, m_hi = -1e30f, l_lo = 0.f, l_hi = 0.f;
    float oacc[8][4];
    #pragma unroll
    for (int nf = 0; nf < 8; nf++)
        #pragma unroll
        for (int r = 0; r < 4; r++) oacc[nf][r] = 0.f;

    const int nkt = qt + 1;
    for (int kt = 0; kt < nkt; kt++) {
        const int buf = kt & 1;
        const int k0  = kt * 128;
        CP_WAIT0();
        __syncthreads();
        if (kt + 1 < nkt) issueKV(kt + 1, buf ^ 1);

        const __half* Kb = Kh + buf * KT_HALVES;
        const __half* Vb = Vh + buf * VT_HALVES;

        // ---- S = (Q/8) K^T : 16x128 per warp ----
        float sacc[16][4];
        #pragma unroll
        for (int nf = 0; nf < 16; nf++)
            #pragma unroll
            for (int r = 0; r < 4; r++) sacc[nf][r] = 0.f;

        #pragma unroll
        for (int ks = 0; ks < 4; ks++) {
            int kk = ks * 16;
            #pragma unroll
            for (int nf = 0; nf < 16; nf++) {
                unsigned b0 = ldh2(&Kb[(nf*8 + g) * KSH + kk + 2*t]);
                unsigned b1 = ldh2(&Kb[(nf*8 + g) * KSH + kk + 8 + 2*t]);
                mma_f16(sacc[nf], qa[ks][0], qa[ks][1], qa[ks][2], qa[ks][3], b0, b1);
            }
        }

        // ---- causal mask (diagonal tile only) ----
        if (kt == nkt - 1) {
            const int rlo = q0 + rb + g;
            #pragma unroll
            for (int nf = 0; nf < 16; nf++) {
                int c0 = k0 + nf*8 + 2*t;
                int c1 = c0 + 1;
                if (c0 > rlo)     sacc[nf][0] = -1e30f;
                if (c1 > rlo)     sacc[nf][1] = -1e30f;
                if (c0 > rlo + 8) sacc[nf][2] = -1e30f;
                if (c1 > rlo + 8) sacc[nf][3] = -1e30f;
            }
        }

        // ---- online softmax (rows g and g+8) ----
        float mx_lo = -1e30f, mx_hi = -1e30f;
        #pragma unroll
        for (int nf = 0; nf < 16; nf++) {
            mx_lo = fmaxf(mx_lo, fmaxf(sacc[nf][0], sacc[nf][1]));
            mx_hi = fmaxf(mx_hi, fmaxf(sacc[nf][2], sacc[nf][3]));
        }
        mx_lo = fmaxf(mx_lo, __shfl_xor_sync(0xffffffffu, mx_lo, 1));
        mx_lo = fmaxf(mx_lo, __shfl_xor_sync(0xffffffffu, mx_lo, 2));
        mx_hi = fmaxf(mx_hi, __shfl_xor_sync(0xffffffffu, mx_hi, 1));
        mx_hi = fmaxf(mx_hi, __shfl_xor_sync(0xffffffffu, mx_hi, 2));

        float mn_lo = fmaxf(m_lo, mx_lo);
        float mn_hi = fmaxf(m_hi, mx_hi);
        float r_lo  = __expf(m_lo - mn_lo);
        float r_hi  = __expf(m_hi - mn_hi);

        float sum_lo = 0.f, sum_hi = 0.f;
        #pragma unroll
        for (int nf = 0; nf < 16; nf++) {
            sacc[nf][0] = __expf(sacc[nf][0] - mn_lo);
            sacc[nf][1] = __expf(sacc[nf][1] - mn_lo);
            sacc[nf][2] = __expf(sacc[nf][2] - mn_hi);
            sacc[nf][3] = __expf(sacc[nf][3] - mn_hi);
            sum_lo += sacc[nf][0] + sacc[nf][1];
            sum_hi += sacc[nf][2] + sacc[nf][3];
        }
        sum_lo += __shfl_xor_sync(0xffffffffu, sum_lo, 1);
        sum_lo += __shfl_xor_sync(0xffffffffu, sum_lo, 2);
        sum_hi += __shfl_xor_sync(0xffffffffu, sum_hi, 1);
        sum_hi += __shfl_xor_sync(0xffffffffu, sum_hi, 2);

        l_lo = l_lo * r_lo + sum_lo;  m_lo = mn_lo;
        l_hi = l_hi * r_hi + sum_hi;  m_hi = mn_hi;

        #pragma unroll
        for (int nf = 0; nf < 8; nf++) {
            oacc[nf][0] *= r_lo;  oacc[nf][1] *= r_lo;
            oacc[nf][2] *= r_hi;  oacc[nf][3] *= r_hi;
        }

        // ---- store P (half2) into warp-private rows of Ph ----
        #pragma unroll
        for (int nf = 0; nf < 16; nf++) {
            *(__half2*)&Ph[(rb + g)     * PSH + nf*8 + 2*t] =
                __floats2half2_rn(sacc[nf][0], sacc[nf][1]);
            *(__half2*)&Ph[(rb + g + 8) * PSH + nf*8 + 2*t] =
                __floats2half2_rn(sacc[nf][2], sacc[nf][3]);
        }
        __syncwarp();

        // ---- O += P V : A=P[16x128], B=Vt[d][j] ----
        #pragma unroll
        for (int ks = 0; ks < 8; ks++) {
            int kk = ks * 16;
            unsigned p0 = ldh2(&Ph[(rb + g)     * PSH + kk + 2*t]);
            unsigned p1 = ldh2(&Ph[(rb + g + 8) * PSH + kk + 2*t]);
            unsigned p2 = ldh2(&Ph[(rb + g)     * PSH + kk + 8 + 2*t]);
            unsigned p3 = ldh2(&Ph[(rb + g + 8) * PSH + kk + 8 + 2*t]);
            #pragma unroll
            for (int nf = 0; nf < 8; nf++) {
                unsigned b0 = ldh2(&Vb[(nf*8 + g) * VSH + kk + 2*t]);
                unsigned b1 = ldh2(&Vb[(nf*8 + g) * VSH + kk + 8 + 2*t]);
                mma_f16(oacc[nf], p0, p1, p2, p3, b0, b1);
            }
        }
    }

    // ---- epilogue: normalize, write half ctx [b,s,h,d] ----
    const float inv_lo = 1.f / l_lo;
    const float inv_hi = 1.f / l_hi;
    #pragma unroll
    for (int nf = 0; nf < 8; nf++) {
        size_t off = (size_t)(b*S_ + q0 + rb + g) * D_ + h*HD_ + nf*8 + 2*t;
        *(__half2*)&g_cth[off] =
            __floats2half2_rn(oacc[nf][0] * inv_lo, oacc[nf][1] * inv_lo);
        *(__half2*)&g_cth[off + (size_t)8 * D_] =
            __floats2half2_rn(oacc[nf][2] * inv_hi, oacc[nf][3] * inv_hi);
    }
}

// ---------------------------------------------------------------------------
extern "C" void kernel_launch(void* const* d_in, const int* in_sizes, int n_in,
                              void* d_out, int out_size)
{
    const float* x    = (const float*)d_in[0];
    const float* cosb = (const float*)d_in[1];
    const float* sinb = (const float*)d_in[2];
    // d_in[3] = attn_mask (causal; implemented analytically)
    const float* Wq = (const float*)d_in[4];
    const float* bq = (const float*)d_in[5];
    const float* Wk = (const float*)d_in[6];
    const float* bk = (const float*)d_in[7];
    const float* Wv = (const float*)d_in[8];
    const float* bv = (const float*)d_in[9];
    const float* Wo = (const float*)d_in[10];
    const float* bo = (const float*)d_in[11];
    float* out = (float*)d_out;

    float *q, *k, *v;
    __half *xh, *wqh, *wkh, *wvh, *woh, *cth;
    cudaGetSymbolAddress((void**)&q,   g_q);
    cudaGetSymbolAddress((void**)&k,   g_k);
    cudaGetSymbolAddress((void**)&v,   g_v);
    cudaGetSymbolAddress((void**)&xh,  g_xh);
    cudaGetSymbolAddress((void**)&wqh, g_wqh);
    cudaGetSymbolAddress((void**)&wkh, g_wkh);
    cudaGetSymbolAddress((void**)&wvh, g_wvh);
    cudaGetSymbolAddress((void**)&woh, g_woh);
    cudaGetSymbolAddress((void**)&cth, g_cth);

    cudaFuncSetAttribute(gemm_h,
                         cudaFuncAttributeMaxDynamicSharedMemorySize,
                         GEMM_SMEM_BYTES);
    cudaFuncSetAttribute(attn_h,
                         cudaFuncAttributeMaxDynamicSharedMemorySize,
                         ATT_SMEM_BYTES);

    // convert inputs to half
    f2h_kernel<<<(M_*D_/4 + 255)/256, 256>>>(x, xh, M_*D_/4);
    f2h_kernel<<<(D_*D_/4 + 255)/256, 256>>>(Wq, wqh, D_*D_/4);
    f2h_kernel<<<(D_*D_/4 + 255)/256, 256>>>(Wk, wkh, D_*D_/4);
    f2h_kernel<<<(D_*D_/4 + 255)/256, 256>>>(Wv, wvh, D_*D_/4);
    f2h_kernel<<<(D_*D_/4 + 255)/256, 256>>>(Wo, woh, D_*D_/4);

    dim3 gg(D_/128, M_/256);   // (8, 32)
    gemm_h<<<gg, 512, GEMM_SMEM_BYTES>>>(xh, wqh, bq, q);
    gemm_h<<<gg, 512, GEMM_SMEM_BYTES>>>(xh, wkh, bk, k);
    gemm_h<<<gg, 512, GEMM_SMEM_BYTES>>>(xh, wvh, bv, v);

    rotary_h_kernel<<<(M_*H_*32)/256, 256>>>(cosb, sinb);
    vtrans_kernel<<<dim3(B_*H_, S_/64), 256>>>();

    attn_h<<<dim3(S_/128, B_*H_), 256, ATT_SMEM_BYTES>>>();

    gemm_h<<<gg, 512, GEMM_SMEM_BYTES>>>(cth, woh, bo, out);
}

// round 13
// speedup vs baseline: 5.5667x; 1.0522x over previous
#include <cuda_runtime.h>
#include <cuda_fp16.h>
#include <math.h>

#define B_  4
#define S_  2048
#define D_  1024
#define H_  16
#define HD_ 64
#define M_  (B_*S_)

// Scratch (allocation-free rule: __device__ globals)
__device__ __half g_xh[M_*D_];         // half input x
__device__ __half g_wqh[D_*D_];
__device__ __half g_wkh[D_*D_];
__device__ __half g_wvh[D_*D_];
__device__ __half g_woh[D_*D_];
__device__ __half g_prq[M_*D_];        // projection outputs (half)
__device__ __half g_prk[M_*D_];
__device__ __half g_prv[M_*D_];
__device__ __half g_qh[M_*D_];         // rotary'd, x0.125
__device__ __half g_kh[M_*D_];
__device__ __half g_vt[M_*D_];         // V transposed: [B*H][64][2048]
__device__ __half g_cth[M_*D_];        // attention output (half)

extern __shared__ float dynsm[];

__device__ __forceinline__ void mma_f16(float* c,
                                        unsigned a0, unsigned a1, unsigned a2, unsigned a3,
                                        unsigned b0, unsigned b1)
{
    asm volatile(
        "mma.sync.aligned.m16n8k16.row.col.f32.f16.f16.f32 "
        "{%0,%1,%2,%3}, {%4,%5,%6,%7}, {%8,%9}, {%0,%1,%2,%3};"
        : "+f"(c[0]), "+f"(c[1]), "+f"(c[2]), "+f"(c[3])
        : "r"(a0), "r"(a1), "r"(a2), "r"(a3), "r"(b0), "r"(b1));
}

__device__ __forceinline__ void cpa16(unsigned saddr, const void* gptr) {
    asm volatile("cp.async.cg.shared.global [%0], [%1], 16;" :: "r"(saddr), "l"(gptr));
}
#define CP_COMMIT() asm volatile("cp.async.commit_group;")
#define CP_WAIT0()  asm volatile("cp.async.wait_group 0;")

__device__ __forceinline__ unsigned ldh2(const __half* p) {
    return *(const unsigned*)p;
}

// ---------------------------------------------------------------------------
// fp32 -> half: x (n4x float4 slots) and the 4 weight matrices in one kernel
// family (weights batched by blockIdx.y).
// ---------------------------------------------------------------------------
__global__ __launch_bounds__(256) void f2h_kernel(const float* __restrict__ in,
                                                  __half* __restrict__ out, int n4)
{
    int i = blockIdx.x * blockDim.x + threadIdx.x;
    if (i < n4) {
        float4 v = ((const float4*)in)[i];
        ((__half2*)out)[2*i]     = __floats2half2_rn(v.x, v.y);
        ((__half2*)out)[2*i + 1] = __floats2half2_rn(v.z, v.w);
    }
}

__global__ __launch_bounds__(256) void f2h_w4_kernel(const float* w0, const float* w1,
                                                     const float* w2, const float* w3)
{
    const float* src = (blockIdx.y == 0) ? w0 : (blockIdx.y == 1) ? w1
                     : (blockIdx.y == 2) ? w2 : w3;
    __half* dst = (blockIdx.y == 0) ? g_wqh : (blockIdx.y == 1) ? g_wkh
                : (blockIdx.y == 2) ? g_wvh : g_woh;
    int i = blockIdx.x * blockDim.x + threadIdx.x;   // over D_*D_/4
    float4 v = ((const float4*)src)[i];
    ((__half2*)dst)[2*i]     = __floats2half2_rn(v.x, v.y);
    ((__half2*)dst)[2*i + 1] = __floats2half2_rn(v.z, v.w);
}

// ---------------------------------------------------------------------------
// FP16 GEMM body: out[m,n] = sum_k A[m,k]*W[n,k] + bias[n]
// 256x128 tile, BK=32, 512 threads, m16n8k16, cp.async double-buffered.
// ---------------------------------------------------------------------------
#define ASH 40
#define GA_HALVES (256*ASH)
#define GB_HALVES (128*ASH)
#define GEMM_SMEM_BYTES (2*(GA_HALVES + GB_HALVES)*2)   // 61,440 B

template<bool HALF_OUT>
__device__ __forceinline__ void gemm_body(const __half* __restrict__ A,
                                          const __half* __restrict__ W,
                                          const float* __restrict__ bias,
                                          void* __restrict__ outv)
{
    __half* As = (__half*)dynsm;
    __half* Bs = As + 2 * GA_HALVES;

    const int tid  = threadIdx.x;
    const int warp = tid >> 5;
    const int lane = tid & 31;
    const int g    = lane >> 2;
    const int t    = lane & 3;
    const int wm   = warp & 3;
    const int wn   = warp >> 2;

    const __half* Abase = A + (size_t)(blockIdx.y * 256) * D_;
    const __half* Wbase = W + (size_t)(blockIdx.x * 128) * D_;

    const unsigned sA = (unsigned)__cvta_generic_to_shared(As);
    const unsigned sB = (unsigned)__cvta_generic_to_shared(Bs);

    float acc[4][4][4];
    #pragma unroll
    for (int i = 0; i < 4; i++)
        #pragma unroll
        for (int j = 0; j < 4; j++)
            #pragma unroll
            for (int r = 0; r < 4; r++) acc[i][j][r] = 0.f;

    auto issue = [&](int kt, int buf) {
        const int k0 = kt * 32;
        #pragma unroll
        for (int it = 0; it < 2; it++) {
            int idx = tid + it * 512;
            int row = idx >> 2;
            int ch  = (idx & 3) * 8;
            cpa16(sA + (unsigned)(buf * GA_HALVES + row * ASH + ch) * 2,
                  Abase + (size_t)row * D_ + k0 + ch);
        }
        {
            int row = tid >> 2;
            int ch  = (tid & 3) * 8;
            cpa16(sB + (unsigned)(buf * GB_HALVES + row * ASH + ch) * 2,
                  Wbase + (size_t)row * D_ + k0 + ch);
        }
        CP_COMMIT();
    };

    issue(0, 0);
    const int NKT = D_ / 32;
    for (int kt = 0; kt < NKT; kt++) {
        const int buf = kt & 1;
        CP_WAIT0();
        __syncthreads();
        if (kt + 1 < NKT) issue(kt + 1, buf ^ 1);

        const __half* Ab = As + buf * GA_HALVES;
        const __half* Bb = Bs + buf * GB_HALVES;
        #pragma unroll
        for (int ks = 0; ks < 2; ks++) {
            const int kk = ks * 16;
            unsigned af[4][4], bf[4][2];
            #pragma unroll
            for (int fm = 0; fm < 4; fm++) {
                const int rb = wm * 64 + fm * 16;
                af[fm][0] = ldh2(&Ab[(rb + g)     * ASH + kk + 2*t]);
                af[fm][1] = ldh2(&Ab[(rb + g + 8) * ASH + kk + 2*t]);
                af[fm][2] = ldh2(&Ab[(rb + g)     * ASH + kk + 8 + 2*t]);
                af[fm][3] = ldh2(&Ab[(rb + g + 8) * ASH + kk + 8 + 2*t]);
            }
            #pragma unroll
            for (int fn = 0; fn < 4; fn++) {
                const int nb = wn * 32 + fn * 8;
                bf[fn][0] = ldh2(&Bb[(nb + g) * ASH + kk + 2*t]);
                bf[fn][1] = ldh2(&Bb[(nb + g) * ASH + kk + 8 + 2*t]);
            }
            #pragma unroll
            for (int fm = 0; fm < 4; fm++)
                #pragma unroll
                for (int fn = 0; fn < 4; fn++)
                    mma_f16(acc[fm][fn], af[fm][0], af[fm][1], af[fm][2], af[fm][3],
                            bf[fn][0], bf[fn][1]);
        }
    }

    #pragma unroll
    for (int fm = 0; fm < 4; fm++) {
        const int row = blockIdx.y * 256 + wm * 64 + fm * 16 + g;
        #pragma unroll
        for (int fn = 0; fn < 4; fn++) {
            const int col = blockIdx.x * 128 + wn * 32 + fn * 8 + 2 * t;
            const float bx = bias[col];
            const float by = bias[col + 1];
            if (HALF_OUT) {
                __half* out = (__half*)outv;
                *(__half2*)&out[(size_t)row * D_ + col] =
                    __floats2half2_rn(acc[fm][fn][0] + bx, acc[fm][fn][1] + by);
                *(__half2*)&out[(size_t)(row + 8) * D_ + col] =
                    __floats2half2_rn(acc[fm][fn][2] + bx, acc[fm][fn][3] + by);
            } else {
                float* out = (float*)outv;
                *(float2*)&out[(size_t)row * D_ + col] =
                    make_float2(acc[fm][fn][0] + bx, acc[fm][fn][1] + by);
                *(float2*)&out[(size_t)(row + 8) * D_ + col] =
                    make_float2(acc[fm][fn][2] + bx, acc[fm][fn][3] + by);
            }
        }
    }
}

__global__ __launch_bounds__(512) void gemm_qkv(const float* __restrict__ bq,
                                                const float* __restrict__ bk,
                                                const float* __restrict__ bv)
{
    const int z = blockIdx.z;
    const __half* W   = (z == 0) ? g_wqh : (z == 1) ? g_wkh : g_wvh;
    const float*  bia = (z == 0) ? bq    : (z == 1) ? bk    : bv;
    __half*       out = (z == 0) ? g_prq : (z == 1) ? g_prk : g_prv;
    gemm_body<true>(g_xh, W, bia, out);
}

__global__ __launch_bounds__(512) void gemm_out(const float* __restrict__ bo,
                                                float* __restrict__ out)
{
    gemm_body<false>(g_cth, g_woh, bo, out);
}

// ---------------------------------------------------------------------------
// Rotary: read half projections, write half g_qh (x0.125) and g_kh.
// ---------------------------------------------------------------------------
__global__ __launch_bounds__(256) void rotary_h_kernel(const float* __restrict__ cosb,
                                                       const float* __restrict__ sinb)
{
    int idx = blockIdx.x * blockDim.x + threadIdx.x;
    int j  = idx & 31;
    int h  = (idx >> 5) & 15;
    int ms = idx >> 9;
    int s  = ms & (S_ - 1);

    float c1 = cosb[s*HD_ + j],      s1 = sinb[s*HD_ + j];
    float c2 = cosb[s*HD_ + j + 32], s2 = sinb[s*HD_ + j + 32];

    size_t base = (size_t)ms * D_ + h * HD_;
    float q1 = __half2float(g_prq[base + j]), q2 = __half2float(g_prq[base + j + 32]);
    g_qh[base + j]      = __float2half_rn((q1 * c1 - q2 * s1) * 0.125f);
    g_qh[base + j + 32] = __float2half_rn((q2 * c2 + q1 * s2) * 0.125f);
    float k1 = __half2float(g_prk[base + j]), k2 = __half2float(g_prk[base + j + 32]);
    g_kh[base + j]      = __float2half_rn(k1 * c1 - k2 * s1);
    g_kh[base + j + 32] = __float2half_rn(k2 * c2 + k1 * s2);
}

// ---------------------------------------------------------------------------
// V transpose: half [b,s,h,d] -> half g_vt[bh][d][s]. 64s x 64d tiles.
// ---------------------------------------------------------------------------
__global__ __launch_bounds__(256) void vtrans_kernel()
{
    __shared__ float ts[64][65];
    const int bh = blockIdx.x;
    const int b  = bh >> 4;
    const int h  = bh & 15;
    const int s0 = blockIdx.y * 64;
    const int tid = threadIdx.x;

    #pragma unroll
    for (int it = 0; it < 4; it++) {
        int l  = tid + it * 256;
        int r  = l >> 4;
        int c4 = (l & 15) * 4;
        const __half2* src = (const __half2*)&g_prv[(size_t)(b*S_ + s0 + r) * D_ + h*HD_ + c4];
        float2 v0 = __half22float2(src[0]);
        float2 v1 = __half22float2(src[1]);
        ts[r][c4+0] = v0.x; ts[r][c4+1] = v0.y; ts[r][c4+2] = v1.x; ts[r][c4+3] = v1.y;
    }
    __syncthreads();

    #pragma unroll
    for (int it = 0; it < 2; it++) {
        int l  = tid + it * 256;
        int d  = l >> 3;
        int j8 = (l & 7) * 8;
        __half2* dst = (__half2*)&g_vt[(size_t)(bh*HD_ + d) * S_ + s0 + j8];
        #pragma unroll
        for (int m = 0; m < 4; m++)
            dst[m] = __floats2half2_rn(ts[j8 + 2*m][d], ts[j8 + 2*m + 1][d]);
    }
}

// ---------------------------------------------------------------------------
// FP16 flash attention, causal, Bc=128 loads processed as two 64-wide chunks
// (halves sacc regs -> 2 CTAs/SM). 256 threads (8 warps x 16 rows).
// P buffer [128][72] (Q staged there; rows warp-private for P).
// K [2][128][72]; Vt [2][64][136].
// ---------------------------------------------------------------------------
#define PSH 72
#define KSH 72
#define VSH 136
#define P_HALVES  (128*PSH)
#define KT_HALVES (128*KSH)
#define VT_HALVES (64*VSH)
#define ATT_SMEM_BYTES ((P_HALVES + 2*KT_HALVES + 2*VT_HALVES) * 2)  // 90,112 B

__global__ __launch_bounds__(256, 2) void attn_h()
{
    __half* Ph = (__half*)dynsm;                 // [128][PSH]
    __half* Kh = Ph + P_HALVES;                  // [2][128][KSH]
    __half* Vh = Kh + 2 * KT_HALVES;             // [2][64][VSH]

    const int qt = (int)gridDim.x - 1 - (int)blockIdx.x;  // heavy tiles first
    const int bh = blockIdx.y;
    const int b  = bh >> 4;
    const int h  = bh & 15;
    const int q0 = qt * 128;

    const int tid  = threadIdx.x;
    const int warp = tid >> 5;
    const int lane = tid & 31;
    const int g    = lane >> 2;
    const int t    = lane & 3;
    const int rb   = warp * 16;

    const unsigned sP = (unsigned)__cvta_generic_to_shared(Ph);
    const unsigned sK = (unsigned)__cvta_generic_to_shared(Kh);
    const unsigned sV = (unsigned)__cvta_generic_to_shared(Vh);

    auto issueKV = [&](int kt, int buf) {
        const int k0 = kt * 128;
        #pragma unroll
        for (int it = 0; it < 4; it++) {         // K: 128 rows x 8 chunks
            int idx = tid + it * 256;
            int j   = idx >> 3;
            int ch  = (idx & 7) * 8;
            cpa16(sK + (unsigned)(buf * KT_HALVES + j * KSH + ch) * 2,
                  g_kh + (size_t)(b*S_ + k0 + j) * D_ + h*HD_ + ch);
        }
        #pragma unroll
        for (int it = 0; it < 4; it++) {         // Vt: 64 rows x 16 chunks
            int idx = tid + it * 256;
            int d   = idx >> 4;
            int ch  = (idx & 15) * 8;
            cpa16(sV + (unsigned)(buf * VT_HALVES + d * VSH + ch) * 2,
                  g_vt + (size_t)(bh*HD_ + d) * S_ + k0 + ch);
        }
        CP_COMMIT();
    };

    // stage Q (half, pre-scaled) into P buffer rows, then issue KV0
    #pragma unroll
    for (int it = 0; it < 4; it++) {
        int idx = tid + it * 256;
        int i   = idx >> 3;
        int ch  = (idx & 7) * 8;
        cpa16(sP + (unsigned)(i * PSH + ch) * 2,
              g_qh + (size_t)(b*S_ + q0 + i) * D_ + h*HD_ + ch);
    }
    issueKV(0, 0);
    CP_WAIT0();
    __syncthreads();

    unsigned qa[4][4];
    #pragma unroll
    for (int ks = 0; ks < 4; ks++) {
        int kk = ks * 16;
        qa[ks][0] = ldh2(&Ph[(rb + g)     * PSH + kk + 2*t]);
        qa[ks][1] = ldh2(&Ph[(rb + g + 8) * PSH + kk + 2*t]);
        qa[ks][2] = ldh2(&Ph[(rb + g)     * PSH + kk + 8 + 2*t]);
        qa[ks][3] = ldh2(&Ph[(rb + g + 8) * PSH + kk + 8 + 2*t]);
    }
    // From here Ph rows [rb, rb+16) are warp-private (P buffer, 64 cols).

    float m_lo = -1e30f, m_hi = -1e30f, l_lo = 0.f, l_hi = 0.f;
    float oacc[8][4];
    #pragma unroll
    for (int nf = 0; nf < 8; nf++)
        #pragma unroll
        for (int r = 0; r < 4; r++) oacc[nf][r] = 0.f;

    const int nkt = qt + 1;
    for (int kt = 0; kt < nkt; kt++) {
        const int buf = kt & 1;
        const int k0  = kt * 128;
        CP_WAIT0();
        __syncthreads();
        if (kt + 1 < nkt) issueKV(kt + 1, buf ^ 1);

        const __half* Kb = Kh + buf * KT_HALVES;
        const __half* Vb = Vh + buf * VT_HALVES;

        #pragma unroll
        for (int c = 0; c < 2; c++) {
            const int j0 = c * 64;
            // chunk fully above the diagonal for this warp -> zero contribution
            if (kt == nkt - 1 && j0 > rb + 15) continue;

            // ---- S chunk = (Q/8) K^T : 16x64 per warp ----
            float sacc[8][4];
            #pragma unroll
            for (int nf = 0; nf < 8; nf++)
                #pragma unroll
                for (int r = 0; r < 4; r++) sacc[nf][r] = 0.f;

            #pragma unroll
            for (int ks = 0; ks < 4; ks++) {
                int kk = ks * 16;
                #pragma unroll
                for (int nf = 0; nf < 8; nf++) {
                    unsigned b0 = ldh2(&Kb[(j0 + nf*8 + g) * KSH + kk + 2*t]);
                    unsigned b1 = ldh2(&Kb[(j0 + nf*8 + g) * KSH + kk + 8 + 2*t]);
                    mma_f16(sacc[nf], qa[ks][0], qa[ks][1], qa[ks][2], qa[ks][3], b0, b1);
                }
            }

            // ---- causal mask (diagonal tile only) ----
            if (kt == nkt - 1) {
                const int rlo = q0 + rb + g;
                #pragma unroll
                for (int nf = 0; nf < 8; nf++) {
                    int c0 = k0 + j0 + nf*8 + 2*t;
                    int c1 = c0 + 1;
                    if (c0 > rlo)     sacc[nf][0] = -1e30f;
                    if (c1 > rlo)     sacc[nf][1] = -1e30f;
                    if (c0 > rlo + 8) sacc[nf][2] = -1e30f;
                    if (c1 > rlo + 8) sacc[nf][3] = -1e30f;
                }
            }

            // ---- online softmax (rows g, g+8) over this 64-col chunk ----
            float mx_lo = -1e30f, mx_hi = -1e30f;
            #pragma unroll
            for (int nf = 0; nf < 8; nf++) {
                mx_lo = fmaxf(mx_lo, fmaxf(sacc[nf][0], sacc[nf][1]));
                mx_hi = fmaxf(mx_hi, fmaxf(sacc[nf][2], sacc[nf][3]));
            }
            mx_lo = fmaxf(mx_lo, __shfl_xor_sync(0xffffffffu, mx_lo, 1));
            mx_lo = fmaxf(mx_lo, __shfl_xor_sync(0xffffffffu, mx_lo, 2));
            mx_hi = fmaxf(mx_hi, __shfl_xor_sync(0xffffffffu, mx_hi, 1));
            mx_hi = fmaxf(mx_hi, __shfl_xor_sync(0xffffffffu, mx_hi, 2));

            float mn_lo = fmaxf(m_lo, mx_lo);
            float mn_hi = fmaxf(m_hi, mx_hi);
            float r_lo  = __expf(m_lo - mn_lo);
            float r_hi  = __expf(m_hi - mn_hi);

            float sum_lo = 0.f, sum_hi = 0.f;
            #pragma unroll
            for (int nf = 0; nf < 8; nf++) {
                sacc[nf][0] = __expf(sacc[nf][0] - mn_lo);
                sacc[nf][1] = __expf(sacc[nf][1] - mn_lo);
                sacc[nf][2] = __expf(sacc[nf][2] - mn_hi);
                sacc[nf][3] = __expf(sacc[nf][3] - mn_hi);
                sum_lo += sacc[nf][0] + sacc[nf][1];
                sum_hi += sacc[nf][2] + sacc[nf][3];
            }
            sum_lo += __shfl_xor_sync(0xffffffffu, sum_lo, 1);
            sum_lo += __shfl_xor_sync(0xffffffffu, sum_lo, 2);
            sum_hi += __shfl_xor_sync(0xffffffffu, sum_hi, 1);
            sum_hi += __shfl_xor_sync(0xffffffffu, sum_hi, 2);

            l_lo = l_lo * r_lo + sum_lo;  m_lo = mn_lo;
            l_hi = l_hi * r_hi + sum_hi;  m_hi = mn_hi;

            #pragma unroll
            for (int nf = 0; nf < 8; nf++) {
                oacc[nf][0] *= r_lo;  oacc[nf][1] *= r_lo;
                oacc[nf][2] *= r_hi;  oacc[nf][3] *= r_hi;
            }

            // ---- store P chunk (half2) into warp-private rows of Ph ----
            #pragma unroll
            for (int nf = 0; nf < 8; nf++) {
                *(__half2*)&Ph[(rb + g)     * PSH + nf*8 + 2*t] =
                    __floats2half2_rn(sacc[nf][0], sacc[nf][1]);
                *(__half2*)&Ph[(rb + g + 8) * PSH + nf*8 + 2*t] =
                    __floats2half2_rn(sacc[nf][2], sacc[nf][3]);
            }
            __syncwarp();

            // ---- O += P V : A=P[16x64], B=Vt[d][j0+..] ----
            #pragma unroll
            for (int ks = 0; ks < 4; ks++) {
                int kk = ks * 16;
                unsigned p0 = ldh2(&Ph[(rb + g)     * PSH + kk + 2*t]);
                unsigned p1 = ldh2(&Ph[(rb + g + 8) * PSH + kk + 2*t]);
                unsigned p2 = ldh2(&Ph[(rb + g)     * PSH + kk + 8 + 2*t]);
                unsigned p3 = ldh2(&Ph[(rb + g + 8) * PSH + kk + 8 + 2*t]);
                #pragma unroll
                for (int nf = 0; nf < 8; nf++) {
                    unsigned b0 = ldh2(&Vb[(nf*8 + g) * VSH + j0 + kk + 2*t]);
                    unsigned b1 = ldh2(&Vb[(nf*8 + g) * VSH + j0 + kk + 8 + 2*t]);
                    mma_f16(oacc[nf], p0, p1, p2, p3, b0, b1);
                }
            }
            __syncwarp();   // P reads done before next chunk overwrites Ph
        }
    }

    // ---- epilogue: normalize, write half ctx [b,s,h,d] ----
    const float inv_lo = 1.f / l_lo;
    const float inv_hi = 1.f / l_hi;
    #pragma unroll
    for (int nf = 0; nf < 8; nf++) {
        size_t off = (size_t)(b*S_ + q0 + rb + g) * D_ + h*HD_ + nf*8 + 2*t;
        *(__half2*)&g_cth[off] =
            __floats2half2_rn(oacc[nf][0] * inv_lo, oacc[nf][1] * inv_lo);
        *(__half2*)&g_cth[off + (size_t)8 * D_] =
            __floats2half2_rn(oacc[nf][2] * inv_hi, oacc[nf][3] * inv_hi);
    }
}

// ---------------------------------------------------------------------------
extern "C" void kernel_launch(void* const* d_in, const int* in_sizes, int n_in,
                              void* d_out, int out_size)
{
    const float* x    = (const float*)d_in[0];
    const float* cosb = (const float*)d_in[1];
    const float* sinb = (const float*)d_in[2];
    // d_in[3] = attn_mask (causal; implemented analytically)
    const float* Wq = (const float*)d_in[4];
    const float* bq = (const float*)d_in[5];
    const float* Wk = (const float*)d_in[6];
    const float* bk = (const float*)d_in[7];
    const float* Wv = (const float*)d_in[8];
    const float* bv = (const float*)d_in[9];
    const float* Wo = (const float*)d_in[10];
    const float* bo = (const float*)d_in[11];
    float* out = (float*)d_out;

    __half* xh;
    cudaGetSymbolAddress((void**)&xh, g_xh);

    cudaFuncSetAttribute(gemm_qkv,
                         cudaFuncAttributeMaxDynamicSharedMemorySize,
                         GEMM_SMEM_BYTES);
    cudaFuncSetAttribute(gemm_out,
                         cudaFuncAttributeMaxDynamicSharedMemorySize,
                         GEMM_SMEM_BYTES);
    cudaFuncSetAttribute(attn_h,
                         cudaFuncAttributeMaxDynamicSharedMemorySize,
                         ATT_SMEM_BYTES);

    // convert inputs to half
    f2h_kernel<<<(M_*D_/4 + 255)/256, 256>>>(x, xh, M_*D_/4);
    f2h_w4_kernel<<<dim3(D_*D_/4/256, 4), 256>>>(Wq, Wk, Wv, Wo);

    // fused QKV projections
    gemm_qkv<<<dim3(D_/128, M_/256, 3), 512, GEMM_SMEM_BYTES>>>(bq, bk, bv);

    rotary_h_kernel<<<(M_*H_*32)/256, 256>>>(cosb, sinb);
    vtrans_kernel<<<dim3(B_*H_, S_/64), 256>>>();

    attn_h<<<dim3(S_/128, B_*H_), 256, ATT_SMEM_BYTES>>>();

    gemm_out<<<dim3(D_/128, M_/256), 512, GEMM_SMEM_BYTES>>>(bo, out);
}